// round 7
// baseline (speedup 1.0000x reference)
#include <cuda_runtime.h>
#include <cuda_bf16.h>
#include <math.h>

// ---- problem constants ----
#define BB 2
#define SS 1024
#define DD 2048
#define HH 16
#define KVHH 4
#define HDD 128
#define EE 64
#define TOPKK 8
#define FF 768
#define TT (BB*SS)          // 2048 tokens
#define QSTR (HH*HDD)       // 2048
#define KSTR (KVHH*HDD)     // 512

// ---- scratch (device globals; no allocation allowed) ----
__device__ float g_h  [(size_t)TT*DD];        // rmsnorm1 output
__device__ float g_q  [(size_t)TT*QSTR];      // Q (post norm+rope, in place)
__device__ float g_kb [(size_t)TT*KSTR];      // K
__device__ float g_vb [(size_t)TT*KSTR];      // V
__device__ float g_o  [(size_t)TT*QSTR];      // attention out
__device__ float g_ht [(size_t)TT*DD];        // rmsnorm2 output
__device__ int   g_topi[TT*TOPKK];
__device__ float g_topv[TT*TOPKK];
__device__ int   g_cnt [EE];
__device__ int   g_list[EE*TT];
__device__ float g_act [(size_t)TT*TOPKK*FF]; // silu(g)*u per pair
__device__ float g_y   [(size_t)TT*TOPKK*DD]; // per-pair down output

// 4x4 outer-product into a sub-block of an accumulator array
#define OUT4(AC,RO,CO,av,bv) \
  AC[RO+0][CO+0]+=av.x*bv.x; AC[RO+0][CO+1]+=av.x*bv.y; AC[RO+0][CO+2]+=av.x*bv.z; AC[RO+0][CO+3]+=av.x*bv.w; \
  AC[RO+1][CO+0]+=av.y*bv.x; AC[RO+1][CO+1]+=av.y*bv.y; AC[RO+1][CO+2]+=av.y*bv.z; AC[RO+1][CO+3]+=av.y*bv.w; \
  AC[RO+2][CO+0]+=av.z*bv.x; AC[RO+2][CO+1]+=av.z*bv.y; AC[RO+2][CO+2]+=av.z*bv.z; AC[RO+2][CO+3]+=av.z*bv.w; \
  AC[RO+3][CO+0]+=av.w*bv.x; AC[RO+3][CO+1]+=av.w*bv.y; AC[RO+3][CO+2]+=av.w*bv.z; AC[RO+3][CO+3]+=av.w*bv.w;

// ================= RMSNorm over D=2048, one block per row =================
__global__ void rmsnorm_k(const float* __restrict__ x, const float* __restrict__ w,
                          float* __restrict__ out){
  int row=blockIdx.x, tid=threadIdx.x;
  const float4* xr=(const float4*)(x+(size_t)row*DD);
  float4 v0=xr[tid], v1=xr[tid+256];
  float ss=v0.x*v0.x+v0.y*v0.y+v0.z*v0.z+v0.w*v0.w
          +v1.x*v1.x+v1.y*v1.y+v1.z*v1.z+v1.w*v1.w;
  #pragma unroll
  for(int off=16;off;off>>=1) ss+=__shfl_xor_sync(0xffffffffu,ss,off);
  __shared__ float red[8];
  if((tid&31)==0) red[tid>>5]=ss;
  __syncthreads();
  float tot=red[0]+red[1]+red[2]+red[3]+red[4]+red[5]+red[6]+red[7];
  float r=rsqrtf(tot/(float)DD + 1e-6f);
  const float4* w4=(const float4*)w;
  float4 wa=w4[tid], wb=w4[tid+256];
  float4 o0={v0.x*r*wa.x, v0.y*r*wa.y, v0.z*r*wa.z, v0.w*r*wa.w};
  float4 o1={v1.x*r*wb.x, v1.y*r*wb.y, v1.z*r*wb.z, v1.w*r*wb.w};
  float4* orow=(float4*)(out+(size_t)row*DD);
  orow[tid]=o0; orow[tid+256]=o1;
}

// ==== GEMM core: 128x128 tile, 8x8 micro, k-tile 8, double-buffered ====
__device__ __forceinline__ void gemm128_core(
    const float* __restrict__ Aptr, const float* __restrict__ Bptr,
    const float* __restrict__ Cadd, float* __restrict__ C,
    int N, int Kd, int m0, int n0, int tid,
    float As[2][8][132], float Bs[2][8][132]){
  int tx=tid&15, ty=tid>>4;
  int arow=tid>>1, akk=(tid&1)<<2;
  int brow=tid>>5, bcol=(tid&31)<<2;
  float acc[8][8]={};
  // preload tile 0
  {
    float4 a=*(const float4*)(Aptr);
    As[0][akk  ][arow]=a.x; As[0][akk+1][arow]=a.y; As[0][akk+2][arow]=a.z; As[0][akk+3][arow]=a.w;
    *(float4*)&Bs[0][brow][bcol]=*(const float4*)(Bptr);
  }
  __syncthreads();
  int cur=0;
  for(int k0=0;k0<Kd;k0+=8){
    bool has=(k0+8)<Kd;
    float4 an,bn;
    if(has){
      an=*(const float4*)(Aptr+k0+8);
      bn=*(const float4*)(Bptr+(size_t)(k0+8)*N);
    }
    #pragma unroll
    for(int kk=0;kk<8;kk++){
      float4 a0=*(float4*)&As[cur][kk][ty<<2];
      float4 a1=*(float4*)&As[cur][kk][64+(ty<<2)];
      float4 b0=*(float4*)&Bs[cur][kk][tx<<2];
      float4 b1=*(float4*)&Bs[cur][kk][64+(tx<<2)];
      OUT4(acc,0,0,a0,b0) OUT4(acc,0,4,a0,b1)
      OUT4(acc,4,0,a1,b0) OUT4(acc,4,4,a1,b1)
    }
    if(has){
      int nx=cur^1;
      As[nx][akk  ][arow]=an.x; As[nx][akk+1][arow]=an.y; As[nx][akk+2][arow]=an.z; As[nx][akk+3][arow]=an.w;
      *(float4*)&Bs[nx][brow][bcol]=bn;
    }
    __syncthreads();
    cur^=1;
  }
  #pragma unroll
  for(int ii=0;ii<2;ii++)
    #pragma unroll
    for(int i=0;i<4;i++){
      int row=m0+(ii<<6)+(ty<<2)+i;
      #pragma unroll
      for(int jj=0;jj<2;jj++){
        size_t off=(size_t)row*N + n0+(jj<<6)+(tx<<2);
        float4 r={acc[(ii<<2)+i][(jj<<2)+0],acc[(ii<<2)+i][(jj<<2)+1],
                  acc[(ii<<2)+i][(jj<<2)+2],acc[(ii<<2)+i][(jj<<2)+3]};
        if(Cadd){ float4 c=*(const float4*)(Cadd+off); r.x+=c.x;r.y+=c.y;r.z+=c.z;r.w+=c.w; }
        *(float4*)(C+off)=r;
      }
    }
}

// generic single-GEMM wrapper (used for wo projection)
__global__ void __launch_bounds__(256,2)
sgemm128(const float* __restrict__ A, const float* __restrict__ B,
         const float* __restrict__ Cadd, float* __restrict__ C,
         int N, int Kd){
  __shared__ float As[2][8][132];
  __shared__ float Bs[2][8][132];
  int tid=threadIdx.x;
  int m0=blockIdx.y<<7, n0=blockIdx.x<<7;
  int arow=tid>>1, akk=(tid&1)<<2;
  int brow=tid>>5, bcol=(tid&31)<<2;
  gemm128_core(A+(size_t)(m0+arow)*Kd+akk, B+(size_t)brow*N+n0+bcol,
               Cadd, C, N, Kd, m0, n0, tid, As, Bs);
}

// fused Q/K/V projection: one launch, 24 n-blocks (16 Q, 4 K, 4 V) x 16 m-blocks
__global__ void __launch_bounds__(256,2)
sgemm_qkv(const float* __restrict__ A,
          const float* __restrict__ wq, const float* __restrict__ wk,
          const float* __restrict__ wv,
          float* __restrict__ q, float* __restrict__ k, float* __restrict__ v){
  __shared__ float As[2][8][132];
  __shared__ float Bs[2][8][132];
  int tid=threadIdx.x;
  int nb=blockIdx.x;
  const float* B; float* C; int N; int n0;
  if(nb<16){ B=wq; C=q; N=QSTR; n0=nb<<7; }
  else if(nb<20){ B=wk; C=k; N=KSTR; n0=(nb-16)<<7; }
  else { B=wv; C=v; N=KSTR; n0=(nb-20)<<7; }
  int m0=blockIdx.y<<7;
  int arow=tid>>1, akk=(tid&1)<<2;
  int brow=tid>>5, bcol=(tid&31)<<2;
  gemm128_core(A+(size_t)(m0+arow)*DD+akk, B+(size_t)brow*N+n0+bcol,
               nullptr, C, N, DD, m0, n0, tid, As, Bs);
}

// ============ per-head RMSNorm + RoPE, in place, q and k ============
__global__ void qknorm_rope_k(const float* __restrict__ cosp, const float* __restrict__ sinp,
                              const float* __restrict__ qnw, const float* __restrict__ knw){
  int t=blockIdx.x, yy=blockIdx.y, i=threadIdx.x;
  float* ptr; const float* w;
  if(yy<HH){ ptr=g_q +(size_t)t*QSTR+yy*HDD; w=qnw; }
  else     { ptr=g_kb+(size_t)t*KSTR+(yy-HH)*HDD; w=knw; }
  float v=ptr[i];
  float ss=v*v;
  #pragma unroll
  for(int off=16;off;off>>=1) ss+=__shfl_xor_sync(0xffffffffu,ss,off);
  __shared__ float red[4];
  __shared__ float sh[HDD];
  if((i&31)==0) red[i>>5]=ss;
  __syncthreads();
  float tot=red[0]+red[1]+red[2]+red[3];
  float n=v*rsqrtf(tot/(float)HDD + 1e-6f)*w[i];
  sh[i]=n;
  __syncthreads();
  float rot=(i<64)? -sh[i+64] : sh[i-64];
  ptr[i]= n*cosp[(size_t)t*HDD+i] + rot*sinp[(size_t)t*HDD+i];
}

// ================= flash attention fp32, BM=BN=64, 256 thr =================
#define FLASH_SMEM ((3*64*132 + 64*68)*4)
__global__ void __launch_bounds__(256,1) flash_k(){
  extern __shared__ float sm[];
  float* Qs=sm;               // [64][132]
  float* Ks=sm+64*132;        // [64][132]
  float* Vs=sm+2*64*132;      // [64][132]
  float* Ps=sm+3*64*132;      // [64][68]
  int tid=threadIdx.x, tx=tid&15, ty=tid>>4;
  int bh=blockIdx.y; int b=bh>>4, h=bh&15, kh=(bh&15)>>2;
  // longest-first scheduling: high-qs0 (most KV tiles) blocks launch first
  int qs0=((SS/64-1)-blockIdx.x)<<6;
  const float scale=0.08838834764831845f; // 1/sqrt(128)

  for(int i=tid;i<64*32;i+=256){
    int r=i>>5, c=(i&31)<<2;
    float4 qv=*(const float4*)(g_q + (size_t)(b*SS+qs0+r)*QSTR + h*HDD + c);
    qv.x*=scale; qv.y*=scale; qv.z*=scale; qv.w*=scale;
    *(float4*)&Qs[r*132+c]=qv;
  }
  float m_r[4], l_r[4], O[4][8];
  #pragma unroll
  for(int i=0;i<4;i++){ m_r[i]=-1e30f; l_r[i]=0.f;
    #pragma unroll
    for(int c=0;c<8;c++) O[i][c]=0.f; }

  for(int j0=0;j0<=qs0;j0+=64){
    for(int i=tid;i<64*32;i+=256){
      int r=i>>5, c=(i&31)<<2;
      size_t kvoff=(size_t)(b*SS+j0+r)*KSTR + kh*HDD + c;
      *(float4*)&Ks[r*132+c]=*(const float4*)(g_kb + kvoff);
      *(float4*)&Vs[r*132+c]=*(const float4*)(g_vb + kvoff);
    }
    __syncthreads();

    float s[4][4]={};
    #pragma unroll 8
    for(int d=0;d<128;d+=4){
      float4 a0=*(float4*)&Qs[((ty<<2)+0)*132+d];
      float4 a1=*(float4*)&Qs[((ty<<2)+1)*132+d];
      float4 a2=*(float4*)&Qs[((ty<<2)+2)*132+d];
      float4 a3=*(float4*)&Qs[((ty<<2)+3)*132+d];
      float4 b0=*(float4*)&Ks[(tx   )*132+d];
      float4 b1=*(float4*)&Ks[(tx+16)*132+d];
      float4 b2=*(float4*)&Ks[(tx+32)*132+d];
      float4 b3=*(float4*)&Ks[(tx+48)*132+d];
      s[0][0]+=a0.x*b0.x+a0.y*b0.y+a0.z*b0.z+a0.w*b0.w;
      s[0][1]+=a0.x*b1.x+a0.y*b1.y+a0.z*b1.z+a0.w*b1.w;
      s[0][2]+=a0.x*b2.x+a0.y*b2.y+a0.z*b2.z+a0.w*b2.w;
      s[0][3]+=a0.x*b3.x+a0.y*b3.y+a0.z*b3.z+a0.w*b3.w;
      s[1][0]+=a1.x*b0.x+a1.y*b0.y+a1.z*b0.z+a1.w*b0.w;
      s[1][1]+=a1.x*b1.x+a1.y*b1.y+a1.z*b1.z+a1.w*b1.w;
      s[1][2]+=a1.x*b2.x+a1.y*b2.y+a1.z*b2.z+a1.w*b2.w;
      s[1][3]+=a1.x*b3.x+a1.y*b3.y+a1.z*b3.z+a1.w*b3.w;
      s[2][0]+=a2.x*b0.x+a2.y*b0.y+a2.z*b0.z+a2.w*b0.w;
      s[2][1]+=a2.x*b1.x+a2.y*b1.y+a2.z*b1.z+a2.w*b1.w;
      s[2][2]+=a2.x*b2.x+a2.y*b2.y+a2.z*b2.z+a2.w*b2.w;
      s[2][3]+=a2.x*b3.x+a2.y*b3.y+a2.z*b3.z+a2.w*b3.w;
      s[3][0]+=a3.x*b0.x+a3.y*b0.y+a3.z*b0.z+a3.w*b0.w;
      s[3][1]+=a3.x*b1.x+a3.y*b1.y+a3.z*b1.z+a3.w*b1.w;
      s[3][2]+=a3.x*b2.x+a3.y*b2.y+a3.z*b2.z+a3.w*b2.w;
      s[3][3]+=a3.x*b3.x+a3.y*b3.y+a3.z*b3.z+a3.w*b3.w;
    }

    if(j0==qs0){ // diagonal tile: causal mask
      #pragma unroll
      for(int i=0;i<4;i++)
        #pragma unroll
        for(int j=0;j<4;j++)
          if(tx + (j<<4) > (ty<<2)+i) s[i][j]=-1e30f;
    }

    #pragma unroll
    for(int i=0;i<4;i++){
      float mx=fmaxf(fmaxf(s[i][0],s[i][1]),fmaxf(s[i][2],s[i][3]));
      #pragma unroll
      for(int off=8;off;off>>=1) mx=fmaxf(mx,__shfl_xor_sync(0xffffffffu,mx,off));
      float mn=fmaxf(m_r[i],mx);
      float sc=__expf(m_r[i]-mn);
      float rs=0.f;
      #pragma unroll
      for(int j=0;j<4;j++){ float p=__expf(s[i][j]-mn); s[i][j]=p; rs+=p; }
      #pragma unroll
      for(int off=8;off;off>>=1) rs+=__shfl_xor_sync(0xffffffffu,rs,off);
      l_r[i]=l_r[i]*sc+rs; m_r[i]=mn;
      #pragma unroll
      for(int c=0;c<8;c++) O[i][c]*=sc;
      #pragma unroll
      for(int j=0;j<4;j++) Ps[((ty<<2)+i)*68 + tx + (j<<4)] = s[i][j];
    }
    __syncthreads();

    #pragma unroll 2
    for(int jj=0;jj<64;jj++){
      float p0=Ps[((ty<<2)+0)*68+jj];
      float p1=Ps[((ty<<2)+1)*68+jj];
      float p2=Ps[((ty<<2)+2)*68+jj];
      float p3=Ps[((ty<<2)+3)*68+jj];
      float4 va=*(float4*)&Vs[jj*132+(tx<<3)];
      float4 vb=*(float4*)&Vs[jj*132+(tx<<3)+4];
      O[0][0]+=p0*va.x; O[0][1]+=p0*va.y; O[0][2]+=p0*va.z; O[0][3]+=p0*va.w;
      O[0][4]+=p0*vb.x; O[0][5]+=p0*vb.y; O[0][6]+=p0*vb.z; O[0][7]+=p0*vb.w;
      O[1][0]+=p1*va.x; O[1][1]+=p1*va.y; O[1][2]+=p1*va.z; O[1][3]+=p1*va.w;
      O[1][4]+=p1*vb.x; O[1][5]+=p1*vb.y; O[1][6]+=p1*vb.z; O[1][7]+=p1*vb.w;
      O[2][0]+=p2*va.x; O[2][1]+=p2*va.y; O[2][2]+=p2*va.z; O[2][3]+=p2*va.w;
      O[2][4]+=p2*vb.x; O[2][5]+=p2*vb.y; O[2][6]+=p2*vb.z; O[2][7]+=p2*vb.w;
      O[3][0]+=p3*va.x; O[3][1]+=p3*va.y; O[3][2]+=p3*va.z; O[3][3]+=p3*va.w;
      O[3][4]+=p3*vb.x; O[3][5]+=p3*vb.y; O[3][6]+=p3*vb.z; O[3][7]+=p3*vb.w;
    }
    __syncthreads();
  }

  #pragma unroll
  for(int i=0;i<4;i++){
    float inv=1.f/l_r[i];
    float* op=g_o + (size_t)(b*SS+qs0+(ty<<2)+i)*QSTR + h*HDD + (tx<<3);
    float4 r0={O[i][0]*inv,O[i][1]*inv,O[i][2]*inv,O[i][3]*inv};
    float4 r1={O[i][4]*inv,O[i][5]*inv,O[i][6]*inv,O[i][7]*inv};
    *(float4*)op=r0; *(float4*)(op+4)=r1;
  }
}

// ====== router: logits + softmax + top-8 (normalized); also zeroes g_cnt ======
__global__ void router_topk_k(const float* __restrict__ rw){
  __shared__ float sh[DD];
  __shared__ float lg[EE];
  int t=blockIdx.x, e=threadIdx.x;
  if(e==0 && t<EE) g_cnt[t]=0;   // folded zero_cnt (read only by later assign_k)
  float4* sh4=(float4*)sh;
  const float4* h4=(const float4*)(g_ht+(size_t)t*DD);
  for(int i=e;i<DD/4;i+=EE) sh4[i]=h4[i];
  __syncthreads();
  float acc=0.f;
  #pragma unroll 4
  for(int d=0;d<DD;d++) acc += sh[d]*rw[(size_t)d*EE+e];
  lg[e]=acc;
  __syncthreads();
  if(e==0){
    float mx=-1e30f;
    for(int i=0;i<EE;i++) mx=fmaxf(mx,lg[i]);
    for(int i=0;i<EE;i++) lg[i]=__expf(lg[i]-mx);
    int ti[TOPKK]; float tv[TOPKK]; float s8=0.f;
    for(int k2=0;k2<TOPKK;k2++){
      float best=-1.f; int bi=0;
      for(int i=0;i<EE;i++) if(lg[i]>best){best=lg[i];bi=i;}
      ti[k2]=bi; tv[k2]=best; s8+=best; lg[bi]=-2.f;
    }
    float inv=1.f/s8;
    for(int k2=0;k2<TOPKK;k2++){ g_topi[t*TOPKK+k2]=ti[k2]; g_topv[t*TOPKK+k2]=tv[k2]*inv; }
  }
}

__global__ void assign_k(){
  int p=blockIdx.x*256+threadIdx.x;
  if(p<TT*TOPKK){
    int e=g_topi[p];
    int pos=atomicAdd(&g_cnt[e],1);
    g_list[e*TT+pos]=p;
  }
}

// == MoE gate+up fused GEMM: tile 128x64, 8x4 dual acc, double-buffered ==
__global__ void __launch_bounds__(256,2)
moe_gateup_k(const float* __restrict__ wg, const float* __restrict__ wu){
  int e=blockIdx.y, n0=blockIdx.x<<6;
  int ce=g_cnt[e];
  if(ce==0) return;
  const float* wge=wg+(size_t)e*DD*FF;
  const float* wue=wu+(size_t)e*DD*FF;
  __shared__ float As[2][8][132], Bg[2][8][68], Bu[2][8][68];
  __shared__ int spair[128], stok[128];
  int tid=threadIdx.x, tx=tid&15, ty=tid>>4;
  int arow=tid>>1, akk=(tid&1)<<2;
  int brow=tid>>5, bcol=(tid&31)<<1;
  for(int m0=0;m0<ce;m0+=128){
    if(tid<128){
      int idx=m0+tid;
      int p=(idx<ce)? g_list[e*TT+idx] : -1;
      spair[tid]=p; stok[tid]=(p>=0)?(p>>3):0;
    }
    __syncthreads();
    int tok=stok[arow];
    const float* Arow=g_ht+(size_t)tok*DD+akk;
    float ag[8][4]={}, au[8][4]={};
    // preload k0=0
    {
      float4 a=*(const float4*)(Arow);
      As[0][akk  ][arow]=a.x; As[0][akk+1][arow]=a.y; As[0][akk+2][arow]=a.z; As[0][akk+3][arow]=a.w;
      *(float2*)&Bg[0][brow][bcol]=*(const float2*)(wge+(size_t)brow*FF+n0+bcol);
      *(float2*)&Bu[0][brow][bcol]=*(const float2*)(wue+(size_t)brow*FF+n0+bcol);
    }
    __syncthreads();
    int cur=0;
    for(int k0=0;k0<DD;k0+=8){
      bool has=(k0+8)<DD;
      float4 an; float2 bgn,bun;
      if(has){
        an =*(const float4*)(Arow+k0+8);
        bgn=*(const float2*)(wge+(size_t)(k0+8+brow)*FF+n0+bcol);
        bun=*(const float2*)(wue+(size_t)(k0+8+brow)*FF+n0+bcol);
      }
      #pragma unroll
      for(int kk=0;kk<8;kk++){
        float4 a0=*(float4*)&As[cur][kk][ty<<2];
        float4 a1=*(float4*)&As[cur][kk][64+(ty<<2)];
        float4 bg=*(float4*)&Bg[cur][kk][tx<<2];
        float4 bu=*(float4*)&Bu[cur][kk][tx<<2];
        OUT4(ag,0,0,a0,bg) OUT4(ag,4,0,a1,bg)
        OUT4(au,0,0,a0,bu) OUT4(au,4,0,a1,bu)
      }
      if(has){
        int nx=cur^1;
        As[nx][akk  ][arow]=an.x; As[nx][akk+1][arow]=an.y; As[nx][akk+2][arow]=an.z; As[nx][akk+3][arow]=an.w;
        *(float2*)&Bg[nx][brow][bcol]=bgn;
        *(float2*)&Bu[nx][brow][bcol]=bun;
      }
      __syncthreads();
      cur^=1;
    }
    #pragma unroll
    for(int ii=0;ii<2;ii++)
      #pragma unroll
      for(int i=0;i<4;i++){
        int p=spair[(ii<<6)+(ty<<2)+i];
        if(p>=0){
          float* dst=g_act+(size_t)p*FF+n0+(tx<<2);
          #pragma unroll
          for(int j=0;j<4;j++){
            float g=ag[(ii<<2)+i][j], u=au[(ii<<2)+i][j];
            dst[j]=(g/(1.f+__expf(-g)))*u;
          }
        }
      }
    __syncthreads();
  }
}

// ==== MoE down GEMM: tile 128x128, 8x8, gathered A rows, double-buffered ====
__global__ void __launch_bounds__(256,2)
moe_down_k(const float* __restrict__ wd){
  int e=blockIdx.y, n0=blockIdx.x<<7;
  int ce=g_cnt[e];
  if(ce==0) return;
  const float* wde=wd+(size_t)e*FF*DD;
  __shared__ float As[2][8][132], Bs[2][8][132];
  __shared__ int spair[128];
  int tid=threadIdx.x, tx=tid&15, ty=tid>>4;
  int arow=tid>>1, akk=(tid&1)<<2;
  int brow=tid>>5, bcol=(tid&31)<<2;
  for(int m0=0;m0<ce;m0+=128){
    if(tid<128){
      int idx=m0+tid;
      spair[tid]=(idx<ce)? g_list[e*TT+idx] : -1;
    }
    __syncthreads();
    int pa=spair[arow]; if(pa<0) pa=0;
    const float* Arow=g_act+(size_t)pa*FF+akk;
    float acc[8][8]={};
    // preload k0=0
    {
      float4 a=*(const float4*)(Arow);
      As[0][akk  ][arow]=a.x; As[0][akk+1][arow]=a.y; As[0][akk+2][arow]=a.z; As[0][akk+3][arow]=a.w;
      *(float4*)&Bs[0][brow][bcol]=*(const float4*)(wde+(size_t)brow*DD+n0+bcol);
    }
    __syncthreads();
    int cur=0;
    for(int k0=0;k0<FF;k0+=8){
      bool has=(k0+8)<FF;
      float4 an,bn;
      if(has){
        an=*(const float4*)(Arow+k0+8);
        bn=*(const float4*)(wde+(size_t)(k0+8+brow)*DD+n0+bcol);
      }
      #pragma unroll
      for(int kk=0;kk<8;kk++){
        float4 a0=*(float4*)&As[cur][kk][ty<<2];
        float4 a1=*(float4*)&As[cur][kk][64+(ty<<2)];
        float4 b0=*(float4*)&Bs[cur][kk][tx<<2];
        float4 b1=*(float4*)&Bs[cur][kk][64+(tx<<2)];
        OUT4(acc,0,0,a0,b0) OUT4(acc,0,4,a0,b1)
        OUT4(acc,4,0,a1,b0) OUT4(acc,4,4,a1,b1)
      }
      if(has){
        int nx=cur^1;
        As[nx][akk  ][arow]=an.x; As[nx][akk+1][arow]=an.y; As[nx][akk+2][arow]=an.z; As[nx][akk+3][arow]=an.w;
        *(float4*)&Bs[nx][brow][bcol]=bn;
      }
      __syncthreads();
      cur^=1;
    }
    #pragma unroll
    for(int ii=0;ii<2;ii++)
      #pragma unroll
      for(int i=0;i<4;i++){
        int p=spair[(ii<<6)+(ty<<2)+i];
        if(p>=0){
          #pragma unroll
          for(int jj=0;jj<2;jj++){
            float4 r={acc[(ii<<2)+i][(jj<<2)+0],acc[(ii<<2)+i][(jj<<2)+1],
                      acc[(ii<<2)+i][(jj<<2)+2],acc[(ii<<2)+i][(jj<<2)+3]};
            *(float4*)(g_y+(size_t)p*DD+n0+(jj<<6)+(tx<<2))=r;
          }
        }
      }
    __syncthreads();
  }
}

// ========== combine: out += sum_k w[t,k] * y[t*8+k, :] ==========
__global__ void combine_k(float* __restrict__ out){
  int t=blockIdx.x;
  __shared__ float w8[TOPKK];
  if(threadIdx.x<TOPKK) w8[threadIdx.x]=g_topv[t*TOPKK+threadIdx.x];
  __syncthreads();
  float4* o4=(float4*)(out+(size_t)t*DD);
  for(int c=threadIdx.x;c<DD/4;c+=blockDim.x){
    float4 a=o4[c];
    #pragma unroll
    for(int k=0;k<TOPKK;k++){
      float wk_=w8[k];
      float4 yv=((const float4*)(g_y+(size_t)(t*TOPKK+k)*DD))[c];
      a.x+=wk_*yv.x; a.y+=wk_*yv.y; a.z+=wk_*yv.z; a.w+=wk_*yv.w;
    }
    o4[c]=a;
  }
}

// =================================================================
extern "C" void kernel_launch(void* const* d_in, const int* in_sizes, int n_in,
                              void* d_out, int out_size){
  const float* x   =(const float*)d_in[0];
  const float* cosp=(const float*)d_in[1];
  const float* sinp=(const float*)d_in[2];
  const float* ln1 =(const float*)d_in[3];
  const float* wq  =(const float*)d_in[4];
  const float* wk  =(const float*)d_in[5];
  const float* wv  =(const float*)d_in[6];
  const float* wo  =(const float*)d_in[7];
  const float* qnw =(const float*)d_in[8];
  const float* knw =(const float*)d_in[9];
  const float* ln2 =(const float*)d_in[10];
  const float* rw  =(const float*)d_in[11];
  const float* wg  =(const float*)d_in[12];
  const float* wu  =(const float*)d_in[13];
  const float* wd  =(const float*)d_in[14];
  float* out=(float*)d_out;

  float *ph,*pq,*pk,*pv,*po,*pht;
  cudaGetSymbolAddress((void**)&ph,  g_h);
  cudaGetSymbolAddress((void**)&pq,  g_q);
  cudaGetSymbolAddress((void**)&pk,  g_kb);
  cudaGetSymbolAddress((void**)&pv,  g_vb);
  cudaGetSymbolAddress((void**)&po,  g_o);
  cudaGetSymbolAddress((void**)&pht, g_ht);

  // 1) h = rmsnorm(x) * ln1_w
  rmsnorm_k<<<TT,256>>>(x, ln1, ph);
  // 2) fused q,k,v projections (one 384-CTA launch)
  sgemm_qkv<<<dim3(24, TT/128),256>>>(ph, wq, wk, wv, pq, pk, pv);
  // 3) per-head rmsnorm + rope (q and k, in place)
  qknorm_rope_k<<<dim3(TT, HH+KVHH),128>>>(cosp, sinp, qnw, knw);
  // 4) causal flash attention (longest-first block order)
  cudaFuncSetAttribute(flash_k, cudaFuncAttributeMaxDynamicSharedMemorySize, FLASH_SMEM);
  flash_k<<<dim3(SS/64, BB*HH),256, FLASH_SMEM>>>();
  // 5) x1 = x + o @ wo   (into d_out)
  sgemm128<<<dim3(DD/128, TT/128),256>>>(po, wo, x, out, DD, QSTR);
  // 6) ht = rmsnorm(x1) * ln2_w
  rmsnorm_k<<<TT,256>>>(out, ln2, pht);
  // 7) router + top-8 (also zeroes g_cnt)
  router_topk_k<<<TT,EE>>>(rw);
  // 8) expert pair lists
  assign_k<<<(TT*TOPKK+255)/256,256>>>();
  // 9) MoE
  moe_gateup_k<<<dim3(FF/64, EE),256>>>(wg, wu);
  moe_down_k  <<<dim3(DD/128, EE),256>>>(wd);
  // 10) out = x1 + weighted expert sum
  combine_k<<<TT,256>>>(out);
}

// round 14
// speedup vs baseline: 1.5520x; 1.5520x over previous
#include <cuda_runtime.h>
#include <cuda_bf16.h>
#include <math.h>
#include <stdint.h>

#define BB 2
#define SS 1024
#define DD 2048
#define HH 16
#define KVHH 4
#define HDD 128
#define EE 64
#define TOPKK 8
#define FF 768
#define TT (BB*SS)
#define QSTR (HH*HDD)
#define KSTR (KVHH*HDD)

// ---- scratch ----
__device__ float g_h  [(size_t)TT*DD];
__device__ float g_q  [(size_t)TT*QSTR];
__device__ float g_kb [(size_t)TT*KSTR];
__device__ float g_vb [(size_t)TT*KSTR];
__device__ float g_o  [(size_t)TT*QSTR];
__device__ float g_ht [(size_t)TT*DD];
__device__ __nv_bfloat16 g_ht_h[(size_t)TT*DD];
__device__ __nv_bfloat16 g_ht_l[(size_t)TT*DD];
__device__ int   g_topi[TT*TOPKK];
__device__ float g_topv[TT*TOPKK];
__device__ int   g_cnt [EE];
__device__ int   g_list[EE*TT];
__device__ __nv_bfloat16 g_act_h[(size_t)TT*TOPKK*FF];
__device__ __nv_bfloat16 g_act_l[(size_t)TT*TOPKK*FF];
__device__ float g_y   [(size_t)TT*TOPKK*DD];
// pre-swizzled bf16 hi/lo weight tiles ([n][k] rows, 128B, SW128)
__device__ __nv_bfloat16 g_wgu_h[(size_t)EE*12*32*8192];
__device__ __nv_bfloat16 g_wgu_l[(size_t)EE*12*32*8192];
__device__ __nv_bfloat16 g_wd_h [(size_t)EE*16*12*8192];
__device__ __nv_bfloat16 g_wd_l [(size_t)EE*16*12*8192];

#define SWZ(o) ((o) ^ (((o)>>3)&0x70))
__device__ __forceinline__ uint32_t smem_u32(const void* p){
  uint32_t a;
  asm("{ .reg .u64 t; cvta.to.shared.u64 t, %1; cvt.u32.u64 %0, t; }" : "=r"(a) : "l"(p));
  return a;
}
__device__ __forceinline__ void split_bf16(float x, __nv_bfloat16& h, __nv_bfloat16& l){
  h = __float2bfloat16_rn(x);
  l = __float2bfloat16_rn(x - __bfloat162float(h));
}

// ---- sm_80-class primitives (NO 'a'-arch features) ----
#define CP_ASYNC16(dst,src) asm volatile("cp.async.cg.shared.global [%0], [%1], 16;" :: "r"((uint32_t)(dst)), "l"(src))
#define CP_COMMIT() asm volatile("cp.async.commit_group;" ::: "memory")
#define CP_WAIT1()  asm volatile("cp.async.wait_group 1;" ::: "memory")
#define LDM4(r,addr) asm volatile("ldmatrix.sync.aligned.m8n8.x4.shared.b16 {%0,%1,%2,%3}, [%4];" \
  : "=r"((r)[0]),"=r"((r)[1]),"=r"((r)[2]),"=r"((r)[3]) : "r"((uint32_t)(addr)))
#define MMA_BF16(d,a,b0,b1) asm volatile( \
  "mma.sync.aligned.m16n8k16.row.col.f32.bf16.bf16.f32 {%0,%1,%2,%3}, {%4,%5,%6,%7}, {%8,%9}, {%0,%1,%2,%3};" \
  : "+f"((d)[0]),"+f"((d)[1]),"+f"((d)[2]),"+f"((d)[3]) \
  : "r"((a)[0]),"r"((a)[1]),"r"((a)[2]),"r"((a)[3]), "r"(b0),"r"(b1))

// smem layout for mma MoE kernels
#define MMS_TILE(s,w) (1024 + ((s)*4+(w))*16384)   // w: 0=Ah 1=Al 2=Bh 3=Bl
#define MMS_TOTAL (1024 + 8*16384)

// ================= RMSNorm (+opt bf16 hi/lo emit) =================
__global__ void rmsnorm_k(const float* __restrict__ x, const float* __restrict__ w,
                          float* __restrict__ out, int write_bf16){
  int row=blockIdx.x, tid=threadIdx.x;
  const float4* xr=(const float4*)(x+(size_t)row*DD);
  float4 v0=xr[tid], v1=xr[tid+256];
  float ss=v0.x*v0.x+v0.y*v0.y+v0.z*v0.z+v0.w*v0.w
          +v1.x*v1.x+v1.y*v1.y+v1.z*v1.z+v1.w*v1.w;
  #pragma unroll
  for(int off=16;off;off>>=1) ss+=__shfl_xor_sync(0xffffffffu,ss,off);
  __shared__ float red[8];
  if((tid&31)==0) red[tid>>5]=ss;
  __syncthreads();
  float tot=red[0]+red[1]+red[2]+red[3]+red[4]+red[5]+red[6]+red[7];
  float r=rsqrtf(tot/(float)DD + 1e-6f);
  const float4* w4=(const float4*)w;
  float4 wa=w4[tid], wb=w4[tid+256];
  float4 o0={v0.x*r*wa.x, v0.y*r*wa.y, v0.z*r*wa.z, v0.w*r*wa.w};
  float4 o1={v1.x*r*wb.x, v1.y*r*wb.y, v1.z*r*wb.z, v1.w*r*wb.w};
  float4* orow=(float4*)(out+(size_t)row*DD);
  orow[tid]=o0; orow[tid+256]=o1;
  if(write_bf16){
    float vs[8]={o0.x,o0.y,o0.z,o0.w,o1.x,o1.y,o1.z,o1.w};
    int base[2]={tid*4, 1024+tid*4};
    #pragma unroll
    for(int g2=0;g2<2;g2++)
      #pragma unroll
      for(int j=0;j<4;j+=2){
        __nv_bfloat16 h0,l0,h1,l1;
        split_bf16(vs[g2*4+j],h0,l0); split_bf16(vs[g2*4+j+1],h1,l1);
        __nv_bfloat162 vh; vh.x=h0; vh.y=h1;
        __nv_bfloat162 vl; vl.x=l0; vl.y=l1;
        size_t o=(size_t)row*DD + base[g2] + j;
        *(__nv_bfloat162*)(g_ht_h+o)=vh;
        *(__nv_bfloat162*)(g_ht_l+o)=vl;
      }
  }
}

// ===== weight conversion: gateup tiles; tile=[128 rows(64g|64u)]x[64 k] =====
__global__ void conv_gu_k(const float* __restrict__ wg, const float* __restrict__ wu){
  __shared__ float st[64][65];
  int kc=blockIdx.x, nb=blockIdx.y, e=blockIdx.z, tid=threadIdx.x;
  size_t toff=((size_t)(e*12+nb)*32 + kc)*8192;
  char* th=(char*)(g_wgu_h+toff);
  char* tl=(char*)(g_wgu_l+toff);
  for(int half=0;half<2;half++){
    const float* src=(half?wu:wg)+(size_t)e*DD*FF;
    for(int idx=tid; idx<64*64; idx+=256){
      int k=idx>>6, n=idx&63;
      st[k][n]=src[(size_t)(kc*64+k)*FF + nb*64 + n];
    }
    __syncthreads();
    for(int idx=tid; idx<64*32; idx+=256){
      int r=idx>>5, c2=idx&31;
      float x0=st[2*c2][r], x1=st[2*c2+1][r];
      __nv_bfloat16 h0,l0,h1,l1;
      split_bf16(x0,h0,l0); split_bf16(x1,h1,l1);
      uint32_t off=SWZ((uint32_t)((half*64+r)*128 + c2*4));
      __nv_bfloat162 vh; vh.x=h0; vh.y=h1;
      __nv_bfloat162 vl; vl.x=l0; vl.y=l1;
      *(__nv_bfloat162*)(th+off)=vh;
      *(__nv_bfloat162*)(tl+off)=vl;
    }
    __syncthreads();
  }
}
// ===== weight conversion: down tiles; tile=[128 rows(D)]x[64 k(F)] =====
__global__ void conv_wd_k(const float* __restrict__ wd){
  __shared__ float st[64][129];
  int kc=blockIdx.x, nb=blockIdx.y, e=blockIdx.z, tid=threadIdx.x;
  size_t toff=((size_t)(e*16+nb)*12 + kc)*8192;
  char* th=(char*)(g_wd_h+toff);
  char* tl=(char*)(g_wd_l+toff);
  const float* src=wd+(size_t)e*FF*DD;
  for(int idx=tid; idx<64*128; idx+=256){
    int k=idx>>7, n=idx&127;
    st[k][n]=src[(size_t)(kc*64+k)*DD + nb*128 + n];
  }
  __syncthreads();
  for(int idx=tid; idx<128*32; idx+=256){
    int r=idx>>5, c2=idx&31;
    float x0=st[2*c2][r], x1=st[2*c2+1][r];
    __nv_bfloat16 h0,l0,h1,l1;
    split_bf16(x0,h0,l0); split_bf16(x1,h1,l1);
    uint32_t off=SWZ((uint32_t)(r*128 + c2*4));
    __nv_bfloat162 vh; vh.x=h0; vh.y=h1;
    __nv_bfloat162 vl; vl.x=l0; vl.y=l1;
    *(__nv_bfloat162*)(th+off)=vh;
    *(__nv_bfloat162*)(tl+off)=vl;
  }
}

#define OUT4(AC,RO,CO,av,bv) \
  AC[RO+0][CO+0]+=av.x*bv.x; AC[RO+0][CO+1]+=av.x*bv.y; AC[RO+0][CO+2]+=av.x*bv.z; AC[RO+0][CO+3]+=av.x*bv.w; \
  AC[RO+1][CO+0]+=av.y*bv.x; AC[RO+1][CO+1]+=av.y*bv.y; AC[RO+1][CO+2]+=av.y*bv.z; AC[RO+1][CO+3]+=av.y*bv.w; \
  AC[RO+2][CO+0]+=av.z*bv.x; AC[RO+2][CO+1]+=av.z*bv.y; AC[RO+2][CO+2]+=av.z*bv.z; AC[RO+2][CO+3]+=av.z*bv.w; \
  AC[RO+3][CO+0]+=av.w*bv.x; AC[RO+3][CO+1]+=av.w*bv.y; AC[RO+3][CO+2]+=av.w*bv.z; AC[RO+3][CO+3]+=av.w*bv.w;

__device__ __forceinline__ void gemm128_core(
    const float* __restrict__ Aptr, const float* __restrict__ Bptr,
    const float* __restrict__ Cadd, float* __restrict__ C,
    int N, int Kd, int m0, int n0, int tid,
    float As[2][8][132], float Bs[2][8][132]){
  int tx=tid&15, ty=tid>>4;
  int arow=tid>>1, akk=(tid&1)<<2;
  int brow=tid>>5, bcol=(tid&31)<<2;
  float acc[8][8]={};
  {
    float4 a=*(const float4*)(Aptr);
    As[0][akk  ][arow]=a.x; As[0][akk+1][arow]=a.y; As[0][akk+2][arow]=a.z; As[0][akk+3][arow]=a.w;
    *(float4*)&Bs[0][brow][bcol]=*(const float4*)(Bptr);
  }
  __syncthreads();
  int cur=0;
  for(int k0=0;k0<Kd;k0+=8){
    bool has=(k0+8)<Kd;
    float4 an,bn;
    if(has){
      an=*(const float4*)(Aptr+k0+8);
      bn=*(const float4*)(Bptr+(size_t)(k0+8)*N);
    }
    #pragma unroll
    for(int kk=0;kk<8;kk++){
      float4 a0=*(float4*)&As[cur][kk][ty<<2];
      float4 a1=*(float4*)&As[cur][kk][64+(ty<<2)];
      float4 b0=*(float4*)&Bs[cur][kk][tx<<2];
      float4 b1=*(float4*)&Bs[cur][kk][64+(tx<<2)];
      OUT4(acc,0,0,a0,b0) OUT4(acc,0,4,a0,b1)
      OUT4(acc,4,0,a1,b0) OUT4(acc,4,4,a1,b1)
    }
    if(has){
      int nx=cur^1;
      As[nx][akk  ][arow]=an.x; As[nx][akk+1][arow]=an.y; As[nx][akk+2][arow]=an.z; As[nx][akk+3][arow]=an.w;
      *(float4*)&Bs[nx][brow][bcol]=bn;
    }
    __syncthreads();
    cur^=1;
  }
  #pragma unroll
  for(int ii=0;ii<2;ii++)
    #pragma unroll
    for(int i=0;i<4;i++){
      int row=m0+(ii<<6)+(ty<<2)+i;
      #pragma unroll
      for(int jj=0;jj<2;jj++){
        size_t off=(size_t)row*N + n0+(jj<<6)+(tx<<2);
        float4 r={acc[(ii<<2)+i][(jj<<2)+0],acc[(ii<<2)+i][(jj<<2)+1],
                  acc[(ii<<2)+i][(jj<<2)+2],acc[(ii<<2)+i][(jj<<2)+3]};
        if(Cadd){ float4 c=*(const float4*)(Cadd+off); r.x+=c.x;r.y+=c.y;r.z+=c.z;r.w+=c.w; }
        *(float4*)(C+off)=r;
      }
    }
}

__global__ void __launch_bounds__(256,2)
sgemm128(const float* __restrict__ A, const float* __restrict__ B,
         const float* __restrict__ Cadd, float* __restrict__ C,
         int N, int Kd){
  __shared__ float As[2][8][132];
  __shared__ float Bs[2][8][132];
  int tid=threadIdx.x;
  int m0=blockIdx.y<<7, n0=blockIdx.x<<7;
  gemm128_core(A+(size_t)(m0+(tid>>1))*Kd+((tid&1)<<2), B+(size_t)(tid>>5)*N+n0+((tid&31)<<2),
               Cadd, C, N, Kd, m0, n0, tid, As, Bs);
}

__global__ void __launch_bounds__(256,2)
sgemm_qkv(const float* __restrict__ A,
          const float* __restrict__ wq, const float* __restrict__ wk,
          const float* __restrict__ wv,
          float* __restrict__ q, float* __restrict__ k, float* __restrict__ v){
  __shared__ float As[2][8][132];
  __shared__ float Bs[2][8][132];
  int tid=threadIdx.x;
  int nb=blockIdx.x;
  const float* B; float* C; int N; int n0;
  if(nb<16){ B=wq; C=q; N=QSTR; n0=nb<<7; }
  else if(nb<20){ B=wk; C=k; N=KSTR; n0=(nb-16)<<7; }
  else { B=wv; C=v; N=KSTR; n0=(nb-20)<<7; }
  int m0=blockIdx.y<<7;
  gemm128_core(A+(size_t)(m0+(tid>>1))*DD+((tid&1)<<2), B+(size_t)(tid>>5)*N+n0+((tid&31)<<2),
               nullptr, C, N, DD, m0, n0, tid, As, Bs);
}

__global__ void qknorm_rope_k(const float* __restrict__ cosp, const float* __restrict__ sinp,
                              const float* __restrict__ qnw, const float* __restrict__ knw){
  int t=blockIdx.x, yy=blockIdx.y, i=threadIdx.x;
  float* ptr; const float* w;
  if(yy<HH){ ptr=g_q +(size_t)t*QSTR+yy*HDD; w=qnw; }
  else     { ptr=g_kb+(size_t)t*KSTR+(yy-HH)*HDD; w=knw; }
  float v=ptr[i];
  float ss=v*v;
  #pragma unroll
  for(int off=16;off;off>>=1) ss+=__shfl_xor_sync(0xffffffffu,ss,off);
  __shared__ float red[4];
  __shared__ float sh[HDD];
  if((i&31)==0) red[i>>5]=ss;
  __syncthreads();
  float tot=red[0]+red[1]+red[2]+red[3];
  float n=v*rsqrtf(tot/(float)HDD + 1e-6f)*w[i];
  sh[i]=n;
  __syncthreads();
  float rot=(i<64)? -sh[i+64] : sh[i-64];
  ptr[i]= n*cosp[(size_t)t*HDD+i] + rot*sinp[(size_t)t*HDD+i];
}

#define FLASH_SMEM ((3*64*132 + 64*68)*4)
__global__ void __launch_bounds__(256,1) flash_k(){
  extern __shared__ float smf[];
  float* Qs=smf;
  float* Ks=smf+64*132;
  float* Vs=smf+2*64*132;
  float* Ps=smf+3*64*132;
  int tid=threadIdx.x, tx=tid&15, ty=tid>>4;
  int bh=blockIdx.y; int b=bh>>4, h=bh&15, kh=(bh&15)>>2;
  int qs0=((SS/64-1)-blockIdx.x)<<6;
  const float scale=0.08838834764831845f;
  for(int i=tid;i<64*32;i+=256){
    int r=i>>5, c=(i&31)<<2;
    float4 qv=*(const float4*)(g_q + (size_t)(b*SS+qs0+r)*QSTR + h*HDD + c);
    qv.x*=scale; qv.y*=scale; qv.z*=scale; qv.w*=scale;
    *(float4*)&Qs[r*132+c]=qv;
  }
  float m_r[4], l_r[4], O[4][8];
  #pragma unroll
  for(int i=0;i<4;i++){ m_r[i]=-1e30f; l_r[i]=0.f;
    #pragma unroll
    for(int c=0;c<8;c++) O[i][c]=0.f; }
  for(int j0=0;j0<=qs0;j0+=64){
    for(int i=tid;i<64*32;i+=256){
      int r=i>>5, c=(i&31)<<2;
      size_t kvoff=(size_t)(b*SS+j0+r)*KSTR + kh*HDD + c;
      *(float4*)&Ks[r*132+c]=*(const float4*)(g_kb + kvoff);
      *(float4*)&Vs[r*132+c]=*(const float4*)(g_vb + kvoff);
    }
    __syncthreads();
    float s[4][4]={};
    #pragma unroll 8
    for(int d=0;d<128;d+=4){
      float4 a0=*(float4*)&Qs[((ty<<2)+0)*132+d];
      float4 a1=*(float4*)&Qs[((ty<<2)+1)*132+d];
      float4 a2=*(float4*)&Qs[((ty<<2)+2)*132+d];
      float4 a3=*(float4*)&Qs[((ty<<2)+3)*132+d];
      float4 b0=*(float4*)&Ks[(tx   )*132+d];
      float4 b1=*(float4*)&Ks[(tx+16)*132+d];
      float4 b2=*(float4*)&Ks[(tx+32)*132+d];
      float4 b3=*(float4*)&Ks[(tx+48)*132+d];
      s[0][0]+=a0.x*b0.x+a0.y*b0.y+a0.z*b0.z+a0.w*b0.w;
      s[0][1]+=a0.x*b1.x+a0.y*b1.y+a0.z*b1.z+a0.w*b1.w;
      s[0][2]+=a0.x*b2.x+a0.y*b2.y+a0.z*b2.z+a0.w*b2.w;
      s[0][3]+=a0.x*b3.x+a0.y*b3.y+a0.z*b3.z+a0.w*b3.w;
      s[1][0]+=a1.x*b0.x+a1.y*b0.y+a1.z*b0.z+a1.w*b0.w;
      s[1][1]+=a1.x*b1.x+a1.y*b1.y+a1.z*b1.z+a1.w*b1.w;
      s[1][2]+=a1.x*b2.x+a1.y*b2.y+a1.z*b2.z+a1.w*b2.w;
      s[1][3]+=a1.x*b3.x+a1.y*b3.y+a1.z*b3.z+a1.w*b3.w;
      s[2][0]+=a2.x*b0.x+a2.y*b0.y+a2.z*b0.z+a2.w*b0.w;
      s[2][1]+=a2.x*b1.x+a2.y*b1.y+a2.z*b1.z+a2.w*b1.w;
      s[2][2]+=a2.x*b2.x+a2.y*b2.y+a2.z*b2.z+a2.w*b2.w;
      s[2][3]+=a2.x*b3.x+a2.y*b3.y+a2.z*b3.z+a2.w*b3.w;
      s[3][0]+=a3.x*b0.x+a3.y*b0.y+a3.z*b0.z+a3.w*b0.w;
      s[3][1]+=a3.x*b1.x+a3.y*b1.y+a3.z*b1.z+a3.w*b1.w;
      s[3][2]+=a3.x*b2.x+a3.y*b2.y+a3.z*b2.z+a3.w*b2.w;
      s[3][3]+=a3.x*b3.x+a3.y*b3.y+a3.z*b3.z+a3.w*b3.w;
    }
    if(j0==qs0){
      #pragma unroll
      for(int i=0;i<4;i++)
        #pragma unroll
        for(int j=0;j<4;j++)
          if(tx + (j<<4) > (ty<<2)+i) s[i][j]=-1e30f;
    }
    #pragma unroll
    for(int i=0;i<4;i++){
      float mx=fmaxf(fmaxf(s[i][0],s[i][1]),fmaxf(s[i][2],s[i][3]));
      #pragma unroll
      for(int off=8;off;off>>=1) mx=fmaxf(mx,__shfl_xor_sync(0xffffffffu,mx,off));
      float mn=fmaxf(m_r[i],mx);
      float sc=__expf(m_r[i]-mn);
      float rs=0.f;
      #pragma unroll
      for(int j=0;j<4;j++){ float p=__expf(s[i][j]-mn); s[i][j]=p; rs+=p; }
      #pragma unroll
      for(int off=8;off;off>>=1) rs+=__shfl_xor_sync(0xffffffffu,rs,off);
      l_r[i]=l_r[i]*sc+rs; m_r[i]=mn;
      #pragma unroll
      for(int c=0;c<8;c++) O[i][c]*=sc;
      #pragma unroll
      for(int j=0;j<4;j++) Ps[((ty<<2)+i)*68 + tx + (j<<4)] = s[i][j];
    }
    __syncthreads();
    #pragma unroll 2
    for(int jj=0;jj<64;jj++){
      float p0=Ps[((ty<<2)+0)*68+jj];
      float p1=Ps[((ty<<2)+1)*68+jj];
      float p2=Ps[((ty<<2)+2)*68+jj];
      float p3=Ps[((ty<<2)+3)*68+jj];
      float4 va=*(float4*)&Vs[jj*132+(tx<<3)];
      float4 vb=*(float4*)&Vs[jj*132+(tx<<3)+4];
      O[0][0]+=p0*va.x; O[0][1]+=p0*va.y; O[0][2]+=p0*va.z; O[0][3]+=p0*va.w;
      O[0][4]+=p0*vb.x; O[0][5]+=p0*vb.y; O[0][6]+=p0*vb.z; O[0][7]+=p0*vb.w;
      O[1][0]+=p1*va.x; O[1][1]+=p1*va.y; O[1][2]+=p1*va.z; O[1][3]+=p1*va.w;
      O[1][4]+=p1*vb.x; O[1][5]+=p1*vb.y; O[1][6]+=p1*vb.z; O[1][7]+=p1*vb.w;
      O[2][0]+=p2*va.x; O[2][1]+=p2*va.y; O[2][2]+=p2*va.z; O[2][3]+=p2*va.w;
      O[2][4]+=p2*vb.x; O[2][5]+=p2*vb.y; O[2][6]+=p2*vb.z; O[2][7]+=p2*vb.w;
      O[3][0]+=p3*va.x; O[3][1]+=p3*va.y; O[3][2]+=p3*va.z; O[3][3]+=p3*va.w;
      O[3][4]+=p3*vb.x; O[3][5]+=p3*vb.y; O[3][6]+=p3*vb.z; O[3][7]+=p3*vb.w;
    }
    __syncthreads();
  }
  #pragma unroll
  for(int i=0;i<4;i++){
    float inv=1.f/l_r[i];
    float* op=g_o + (size_t)(b*SS+qs0+(ty<<2)+i)*QSTR + h*HDD + (tx<<3);
    float4 r0={O[i][0]*inv,O[i][1]*inv,O[i][2]*inv,O[i][3]*inv};
    float4 r1={O[i][4]*inv,O[i][5]*inv,O[i][6]*inv,O[i][7]*inv};
    *(float4*)op=r0; *(float4*)(op+4)=r1;
  }
}

__global__ void router_topk_k(const float* __restrict__ rw){
  __shared__ float sh[DD];
  __shared__ float lg[EE];
  int t=blockIdx.x, e=threadIdx.x;
  if(e==0 && t<EE) g_cnt[t]=0;
  float4* sh4=(float4*)sh;
  const float4* h4=(const float4*)(g_ht+(size_t)t*DD);
  for(int i=e;i<DD/4;i+=EE) sh4[i]=h4[i];
  __syncthreads();
  float acc=0.f;
  #pragma unroll 4
  for(int d=0;d<DD;d++) acc += sh[d]*rw[(size_t)d*EE+e];
  lg[e]=acc;
  __syncthreads();
  if(e==0){
    float mx=-1e30f;
    for(int i=0;i<EE;i++) mx=fmaxf(mx,lg[i]);
    for(int i=0;i<EE;i++) lg[i]=__expf(lg[i]-mx);
    int ti[TOPKK]; float tv[TOPKK]; float s8=0.f;
    for(int k2=0;k2<TOPKK;k2++){
      float best=-1.f; int bi=0;
      for(int i=0;i<EE;i++) if(lg[i]>best){best=lg[i];bi=i;}
      ti[k2]=bi; tv[k2]=best; s8+=best; lg[bi]=-2.f;
    }
    float inv=1.f/s8;
    for(int k2=0;k2<TOPKK;k2++){ g_topi[t*TOPKK+k2]=ti[k2]; g_topv[t*TOPKK+k2]=tv[k2]*inv; }
  }
}

__global__ void assign_k(){
  int p=blockIdx.x*256+threadIdx.x;
  if(p<TT*TOPKK){
    int e=g_topi[p];
    int pos=atomicAdd(&g_cnt[e],1);
    g_list[e*TT+pos]=p;
  }
}

// ====== MoE gate+up via mma.sync bf16x3; CTA=(nb in F/64, e) ======
__global__ void __launch_bounds__(256,1) moe_gateup_mma(){
  extern __shared__ char smraw[];
  int tid=threadIdx.x, lane=tid&31, w=tid>>5;
  int nb=blockIdx.x, e=blockIdx.y;
  int ce=g_cnt[e]; if(ce==0) return;
  uint32_t smb=smem_u32(smraw);
  int* spair_s=(int*)smraw;
  int* stok_s =(int*)(smraw+512);
  const char* BhW=(const char*)(g_wgu_h + (size_t)(e*12+nb)*32*8192);
  const char* BlW=(const char*)(g_wgu_l + (size_t)(e*12+nb)*32*8192);
  int mrow=(w&3)*32, ncol=(w>>2)*32;

  for(int m0=0;m0<ce;m0+=128){
    if(tid<128){
      int idx=m0+tid;
      int p=(idx<ce)? g_list[e*TT+idx] : -1;
      spair_s[tid]=p; stok_s[tid]=(p>=0)?(p>>3):0;
    }
    __syncthreads();
    float accg[2][4][4]={}, accu[2][4][4]={};
    {
      for(int idx=tid; idx<1024; idx+=256){
        int r=idx>>3, c=idx&7;
        size_t src=(size_t)stok_s[r]*DD + c*8;
        uint32_t d=SWZ((uint32_t)(r*128+c*16));
        CP_ASYNC16(smb+MMS_TILE(0,0)+d, (const char*)(g_ht_h+src));
        CP_ASYNC16(smb+MMS_TILE(0,1)+d, (const char*)(g_ht_l+src));
        CP_ASYNC16(smb+MMS_TILE(0,2)+idx*16, BhW+idx*16);
        CP_ASYNC16(smb+MMS_TILE(0,3)+idx*16, BlW+idx*16);
      }
      CP_COMMIT();
    }
    for(int kc=0;kc<32;kc++){
      int s=kc&1;
      if(kc+1<32){
        int ns=s^1, nk=kc+1;
        for(int idx=tid; idx<1024; idx+=256){
          int r=idx>>3, c=idx&7;
          size_t src=(size_t)stok_s[r]*DD + nk*64 + c*8;
          uint32_t d=SWZ((uint32_t)(r*128+c*16));
          CP_ASYNC16(smb+MMS_TILE(ns,0)+d, (const char*)(g_ht_h+src));
          CP_ASYNC16(smb+MMS_TILE(ns,1)+d, (const char*)(g_ht_l+src));
          CP_ASYNC16(smb+MMS_TILE(ns,2)+idx*16, BhW+(size_t)nk*16384+idx*16);
          CP_ASYNC16(smb+MMS_TILE(ns,3)+idx*16, BlW+(size_t)nk*16384+idx*16);
        }
      }
      CP_COMMIT();
      CP_WAIT1();
      __syncthreads();
      uint32_t Ah=smb+MMS_TILE(s,0), Al=smb+MMS_TILE(s,1);
      uint32_t Bh=smb+MMS_TILE(s,2), Bl=smb+MMS_TILE(s,3);
      #pragma unroll
      for(int ks=0;ks<4;ks++){
        uint32_t ah[2][4], al[2][4];
        #pragma unroll
        for(int mt=0;mt<2;mt++){
          uint32_t ra=SWZ((uint32_t)((mrow+mt*16+(lane&15))*128 + ks*32 + ((lane>>4)<<4)));
          LDM4(ah[mt], Ah+ra);
          LDM4(al[mt], Al+ra);
        }
        #pragma unroll
        for(int half=0;half<2;half++){
          #pragma unroll
          for(int np=0;np<2;np++){
            uint32_t rb=SWZ((uint32_t)((half*64+ncol+np*16+(lane&15))*128 + ks*32 + ((lane>>4)<<4)));
            uint32_t bh[4], bl[4];
            LDM4(bh, Bh+rb);
            LDM4(bl, Bl+rb);
            #pragma unroll
            for(int sub=0;sub<2;sub++){
              int nt=np*2+sub;
              #pragma unroll
              for(int mt=0;mt<2;mt++){
                float* acc = half? accu[mt][nt] : accg[mt][nt];
                MMA_BF16(acc, ah[mt], bh[sub], bh[sub+2]);
                MMA_BF16(acc, ah[mt], bl[sub], bl[sub+2]);
                MMA_BF16(acc, al[mt], bh[sub], bh[sub+2]);
              }
            }
          }
        }
      }
      __syncthreads();
    }
    // epilogue: silu(g)*u -> bf16 hi/lo
    #pragma unroll
    for(int mt=0;mt<2;mt++){
      #pragma unroll
      for(int dr=0;dr<2;dr++){
        int rr=mrow+mt*16+(lane>>2)+dr*8;
        int p=spair_s[rr];
        if(p>=0){
          #pragma unroll
          for(int nt=0;nt<4;nt++){
            int col=ncol+nt*8+(lane&3)*2;
            float g0=accg[mt][nt][dr*2],   g1=accg[mt][nt][dr*2+1];
            float u0=accu[mt][nt][dr*2],   u1=accu[mt][nt][dr*2+1];
            float a0=(g0/(1.f+__expf(-g0)))*u0;
            float a1=(g1/(1.f+__expf(-g1)))*u1;
            __nv_bfloat16 h0,l0,h1,l1;
            split_bf16(a0,h0,l0); split_bf16(a1,h1,l1);
            __nv_bfloat162 vh; vh.x=h0; vh.y=h1;
            __nv_bfloat162 vl; vl.x=l0; vl.y=l1;
            size_t o=(size_t)p*FF + nb*64 + col;
            *(__nv_bfloat162*)(g_act_h+o)=vh;
            *(__nv_bfloat162*)(g_act_l+o)=vl;
          }
        }
      }
    }
    __syncthreads();
  }
}

// ====== MoE down via mma.sync bf16x3; CTA=(nb in D/128, e) ======
__global__ void __launch_bounds__(256,1) moe_down_mma(){
  extern __shared__ char smraw[];
  int tid=threadIdx.x, lane=tid&31, w=tid>>5;
  int nb=blockIdx.x, e=blockIdx.y;
  int ce=g_cnt[e]; if(ce==0) return;
  uint32_t smb=smem_u32(smraw);
  int* spair_s=(int*)smraw;
  const char* BhW=(const char*)(g_wd_h + (size_t)(e*16+nb)*12*8192);
  const char* BlW=(const char*)(g_wd_l + (size_t)(e*16+nb)*12*8192);
  int mrow=(w&3)*32, ncol=(w>>2)*64;

  for(int m0=0;m0<ce;m0+=128){
    if(tid<128){
      int idx=m0+tid;
      spair_s[tid]=(idx<ce)? g_list[e*TT+idx] : -1;
    }
    __syncthreads();
    float acc[2][8][4]={};
    {
      for(int idx=tid; idx<1024; idx+=256){
        int r=idx>>3, c=idx&7;
        int p=spair_s[r]; if(p<0) p=0;
        size_t src=(size_t)p*FF + c*8;
        uint32_t d=SWZ((uint32_t)(r*128+c*16));
        CP_ASYNC16(smb+MMS_TILE(0,0)+d, (const char*)(g_act_h+src));
        CP_ASYNC16(smb+MMS_TILE(0,1)+d, (const char*)(g_act_l+src));
        CP_ASYNC16(smb+MMS_TILE(0,2)+idx*16, BhW+idx*16);
        CP_ASYNC16(smb+MMS_TILE(0,3)+idx*16, BlW+idx*16);
      }
      CP_COMMIT();
    }
    for(int kc=0;kc<12;kc++){
      int s=kc&1;
      if(kc+1<12){
        int ns=s^1, nk=kc+1;
        for(int idx=tid; idx<1024; idx+=256){
          int r=idx>>3, c=idx&7;
          int p=spair_s[r]; if(p<0) p=0;
          size_t src=(size_t)p*FF + nk*64 + c*8;
          uint32_t d=SWZ((uint32_t)(r*128+c*16));
          CP_ASYNC16(smb+MMS_TILE(ns,0)+d, (const char*)(g_act_h+src));
          CP_ASYNC16(smb+MMS_TILE(ns,1)+d, (const char*)(g_act_l+src));
          CP_ASYNC16(smb+MMS_TILE(ns,2)+idx*16, BhW+(size_t)nk*16384+idx*16);
          CP_ASYNC16(smb+MMS_TILE(ns,3)+idx*16, BlW+(size_t)nk*16384+idx*16);
        }
      }
      CP_COMMIT();
      CP_WAIT1();
      __syncthreads();
      uint32_t Ah=smb+MMS_TILE(s,0), Al=smb+MMS_TILE(s,1);
      uint32_t Bh=smb+MMS_TILE(s,2), Bl=smb+MMS_TILE(s,3);
      #pragma unroll
      for(int ks=0;ks<4;ks++){
        uint32_t ah[2][4], al[2][4];
        #pragma unroll
        for(int mt=0;mt<2;mt++){
          uint32_t ra=SWZ((uint32_t)((mrow+mt*16+(lane&15))*128 + ks*32 + ((lane>>4)<<4)));
          LDM4(ah[mt], Ah+ra);
          LDM4(al[mt], Al+ra);
        }
        #pragma unroll
        for(int np=0;np<4;np++){
          uint32_t rb=SWZ((uint32_t)((ncol+np*16+(lane&15))*128 + ks*32 + ((lane>>4)<<4)));
          uint32_t bh[4], bl[4];
          LDM4(bh, Bh+rb);
          LDM4(bl, Bl+rb);
          #pragma unroll
          for(int sub=0;sub<2;sub++){
            int nt=np*2+sub;
            #pragma unroll
            for(int mt=0;mt<2;mt++){
              MMA_BF16(acc[mt][nt], ah[mt], bh[sub], bh[sub+2]);
              MMA_BF16(acc[mt][nt], ah[mt], bl[sub], bl[sub+2]);
              MMA_BF16(acc[mt][nt], al[mt], bh[sub], bh[sub+2]);
            }
          }
        }
      }
      __syncthreads();
    }
    #pragma unroll
    for(int mt=0;mt<2;mt++){
      #pragma unroll
      for(int dr=0;dr<2;dr++){
        int rr=mrow+mt*16+(lane>>2)+dr*8;
        int p=spair_s[rr];
        if(p>=0){
          #pragma unroll
          for(int nt=0;nt<8;nt++){
            int col=ncol+nt*8+(lane&3)*2;
            float2 v={acc[mt][nt][dr*2], acc[mt][nt][dr*2+1]};
            *(float2*)(g_y+(size_t)p*DD + nb*128 + col)=v;
          }
        }
      }
    }
    __syncthreads();
  }
}

__global__ void combine_k(float* __restrict__ out){
  int t=blockIdx.x;
  __shared__ float w8[TOPKK];
  if(threadIdx.x<TOPKK) w8[threadIdx.x]=g_topv[t*TOPKK+threadIdx.x];
  __syncthreads();
  float4* o4=(float4*)(out+(size_t)t*DD);
  for(int c=threadIdx.x;c<DD/4;c+=blockDim.x){
    float4 a=o4[c];
    #pragma unroll
    for(int k=0;k<TOPKK;k++){
      float wk_=w8[k];
      float4 yv=((const float4*)(g_y+(size_t)(t*TOPKK+k)*DD))[c];
      a.x+=wk_*yv.x; a.y+=wk_*yv.y; a.z+=wk_*yv.z; a.w+=wk_*yv.w;
    }
    o4[c]=a;
  }
}

// =================================================================
extern "C" void kernel_launch(void* const* d_in, const int* in_sizes, int n_in,
                              void* d_out, int out_size){
  const float* x   =(const float*)d_in[0];
  const float* cosp=(const float*)d_in[1];
  const float* sinp=(const float*)d_in[2];
  const float* ln1 =(const float*)d_in[3];
  const float* wq  =(const float*)d_in[4];
  const float* wk  =(const float*)d_in[5];
  const float* wv  =(const float*)d_in[6];
  const float* wo  =(const float*)d_in[7];
  const float* qnw =(const float*)d_in[8];
  const float* knw =(const float*)d_in[9];
  const float* ln2 =(const float*)d_in[10];
  const float* rw  =(const float*)d_in[11];
  const float* wg  =(const float*)d_in[12];
  const float* wu  =(const float*)d_in[13];
  const float* wd  =(const float*)d_in[14];
  float* out=(float*)d_out;

  float *ph,*pq,*pk,*pv,*po,*pht;
  cudaGetSymbolAddress((void**)&ph,  g_h);
  cudaGetSymbolAddress((void**)&pq,  g_q);
  cudaGetSymbolAddress((void**)&pk,  g_kb);
  cudaGetSymbolAddress((void**)&pv,  g_vb);
  cudaGetSymbolAddress((void**)&po,  g_o);
  cudaGetSymbolAddress((void**)&pht, g_ht);

  cudaFuncSetAttribute(flash_k, cudaFuncAttributeMaxDynamicSharedMemorySize, FLASH_SMEM);
  cudaFuncSetAttribute(moe_gateup_mma, cudaFuncAttributeMaxDynamicSharedMemorySize, MMS_TOTAL);
  cudaFuncSetAttribute(moe_down_mma,   cudaFuncAttributeMaxDynamicSharedMemorySize, MMS_TOTAL);

  // 0) weight conversion -> bf16 hi/lo pre-swizzled tiles
  conv_gu_k<<<dim3(32,12,EE),256>>>(wg, wu);
  conv_wd_k<<<dim3(12,16,EE),256>>>(wd);
  // 1) h = rmsnorm(x)
  rmsnorm_k<<<TT,256>>>(x, ln1, ph, 0);
  // 2) fused q,k,v projections
  sgemm_qkv<<<dim3(24, TT/128),256>>>(ph, wq, wk, wv, pq, pk, pv);
  // 3) per-head rmsnorm + rope
  qknorm_rope_k<<<dim3(TT, HH+KVHH),128>>>(cosp, sinp, qnw, knw);
  // 4) causal flash attention
  flash_k<<<dim3(SS/64, BB*HH),256, FLASH_SMEM>>>();
  // 5) x1 = x + o @ wo (into d_out)
  sgemm128<<<dim3(DD/128, TT/128),256>>>(po, wo, x, out, DD, QSTR);
  // 6) ht = rmsnorm(x1); also emit bf16 hi/lo
  rmsnorm_k<<<TT,256>>>(out, ln2, pht, 1);
  // 7) router + top-8 (also zeroes g_cnt)
  router_topk_k<<<TT,EE>>>(rw);
  // 8) expert pair lists
  assign_k<<<(TT*TOPKK+255)/256,256>>>();
  // 9) MoE on tensor cores (mma.sync bf16x3)
  moe_gateup_mma<<<dim3(12,EE),256,MMS_TOTAL>>>();
  moe_down_mma  <<<dim3(16,EE),256,MMS_TOTAL>>>();
  // 10) out = x1 + weighted expert sum
  combine_k<<<TT,256>>>(out);
}

// round 17
// speedup vs baseline: 1.8111x; 1.1670x over previous
#include <cuda_runtime.h>
#include <cuda_bf16.h>
#include <math.h>
#include <stdint.h>

#define BB 2
#define SS 1024
#define DD 2048
#define HH 16
#define KVHH 4
#define HDD 128
#define EE 64
#define TOPKK 8
#define FF 768
#define TT (BB*SS)
#define QSTR (HH*HDD)
#define KSTR (KVHH*HDD)

// ---- scratch ----
__device__ float g_h  [(size_t)TT*DD];
__device__ float g_q  [(size_t)TT*QSTR];
__device__ float g_kb [(size_t)TT*KSTR];
__device__ float g_vb [(size_t)TT*KSTR];
__device__ float g_o  [(size_t)TT*QSTR];
__device__ __nv_bfloat16 g_o_h[(size_t)TT*QSTR];
__device__ __nv_bfloat16 g_o_l[(size_t)TT*QSTR];
__device__ float g_ht [(size_t)TT*DD];
__device__ __nv_bfloat16 g_ht_h[(size_t)TT*DD];   // reused: rmsnorm1 bf16 (step2), rmsnorm2 bf16 (step9)
__device__ __nv_bfloat16 g_ht_l[(size_t)TT*DD];
__device__ int   g_topi[TT*TOPKK];
__device__ float g_topv[TT*TOPKK];
__device__ int   g_cnt [EE];
__device__ int   g_list[EE*TT];
__device__ __nv_bfloat16 g_act_h[(size_t)TT*TOPKK*FF];
__device__ __nv_bfloat16 g_act_l[(size_t)TT*TOPKK*FF];
__device__ float g_y   [(size_t)TT*TOPKK*DD];
// pre-swizzled bf16 hi/lo weight tiles ([n][k] rows, 128B, SW128)
__device__ __nv_bfloat16 g_wgu_h[(size_t)EE*12*32*8192];
__device__ __nv_bfloat16 g_wgu_l[(size_t)EE*12*32*8192];
__device__ __nv_bfloat16 g_wd_h [(size_t)EE*16*12*8192];
__device__ __nv_bfloat16 g_wd_l [(size_t)EE*16*12*8192];
__device__ __nv_bfloat16 g_wqkv_h[(size_t)24*32*8192];
__device__ __nv_bfloat16 g_wqkv_l[(size_t)24*32*8192];
__device__ __nv_bfloat16 g_wo_h [(size_t)16*32*8192];
__device__ __nv_bfloat16 g_wo_l [(size_t)16*32*8192];

#define SWZ(o) ((o) ^ (((o)>>3)&0x70))
__device__ __forceinline__ uint32_t smem_u32(const void* p){
  uint32_t a;
  asm("{ .reg .u64 t; cvta.to.shared.u64 t, %1; cvt.u32.u64 %0, t; }" : "=r"(a) : "l"(p));
  return a;
}
__device__ __forceinline__ void split_bf16(float x, __nv_bfloat16& h, __nv_bfloat16& l){
  h = __float2bfloat16_rn(x);
  l = __float2bfloat16_rn(x - __bfloat162float(h));
}

// ---- sm_80-class primitives ----
#define CP_ASYNC16(dst,src) asm volatile("cp.async.cg.shared.global [%0], [%1], 16;" :: "r"((uint32_t)(dst)), "l"(src))
#define CP_COMMIT() asm volatile("cp.async.commit_group;" ::: "memory")
#define CP_WAIT1()  asm volatile("cp.async.wait_group 1;" ::: "memory")
#define LDM4(r,addr) asm volatile("ldmatrix.sync.aligned.m8n8.x4.shared.b16 {%0,%1,%2,%3}, [%4];" \
  : "=r"((r)[0]),"=r"((r)[1]),"=r"((r)[2]),"=r"((r)[3]) : "r"((uint32_t)(addr)))
#define MMA_BF16(d,a,b0,b1) asm volatile( \
  "mma.sync.aligned.m16n8k16.row.col.f32.bf16.bf16.f32 {%0,%1,%2,%3}, {%4,%5,%6,%7}, {%8,%9}, {%0,%1,%2,%3};" \
  : "+f"((d)[0]),"+f"((d)[1]),"+f"((d)[2]),"+f"((d)[3]) \
  : "r"((a)[0]),"r"((a)[1]),"r"((a)[2]),"r"((a)[3]), "r"(b0),"r"(b1))

#define MMS_TILE(s,w) (1024 + ((s)*4+(w))*16384)   // w: 0=Ah 1=Al 2=Bh 3=Bl
#define MMS_TOTAL (1024 + 8*16384)

// ================= RMSNorm (+opt bf16 hi/lo emit to g_ht_h/l) =================
__global__ void rmsnorm_k(const float* __restrict__ x, const float* __restrict__ w,
                          float* __restrict__ out, int write_bf16){
  int row=blockIdx.x, tid=threadIdx.x;
  const float4* xr=(const float4*)(x+(size_t)row*DD);
  float4 v0=xr[tid], v1=xr[tid+256];
  float ss=v0.x*v0.x+v0.y*v0.y+v0.z*v0.z+v0.w*v0.w
          +v1.x*v1.x+v1.y*v1.y+v1.z*v1.z+v1.w*v1.w;
  #pragma unroll
  for(int off=16;off;off>>=1) ss+=__shfl_xor_sync(0xffffffffu,ss,off);
  __shared__ float red[8];
  if((tid&31)==0) red[tid>>5]=ss;
  __syncthreads();
  float tot=red[0]+red[1]+red[2]+red[3]+red[4]+red[5]+red[6]+red[7];
  float r=rsqrtf(tot/(float)DD + 1e-6f);
  const float4* w4=(const float4*)w;
  float4 wa=w4[tid], wb=w4[tid+256];
  float4 o0={v0.x*r*wa.x, v0.y*r*wa.y, v0.z*r*wa.z, v0.w*r*wa.w};
  float4 o1={v1.x*r*wb.x, v1.y*r*wb.y, v1.z*r*wb.z, v1.w*r*wb.w};
  float4* orow=(float4*)(out+(size_t)row*DD);
  orow[tid]=o0; orow[tid+256]=o1;
  if(write_bf16){
    float vs[8]={o0.x,o0.y,o0.z,o0.w,o1.x,o1.y,o1.z,o1.w};
    int base[2]={tid*4, 1024+tid*4};
    #pragma unroll
    for(int g2=0;g2<2;g2++)
      #pragma unroll
      for(int j=0;j<4;j+=2){
        __nv_bfloat16 h0,l0,h1,l1;
        split_bf16(vs[g2*4+j],h0,l0); split_bf16(vs[g2*4+j+1],h1,l1);
        __nv_bfloat162 vh; vh.x=h0; vh.y=h1;
        __nv_bfloat162 vl; vl.x=l0; vl.y=l1;
        size_t o=(size_t)row*DD + base[g2] + j;
        *(__nv_bfloat162*)(g_ht_h+o)=vh;
        *(__nv_bfloat162*)(g_ht_l+o)=vl;
      }
  }
}

// ===== weight conversion: gateup tiles; tile=[128 rows(64g|64u)]x[64 k] =====
__global__ void conv_gu_k(const float* __restrict__ wg, const float* __restrict__ wu){
  __shared__ float st[64][65];
  int kc=blockIdx.x, nb=blockIdx.y, e=blockIdx.z, tid=threadIdx.x;
  size_t toff=((size_t)(e*12+nb)*32 + kc)*8192;
  char* th=(char*)(g_wgu_h+toff);
  char* tl=(char*)(g_wgu_l+toff);
  for(int half=0;half<2;half++){
    const float* src=(half?wu:wg)+(size_t)e*DD*FF;
    for(int idx=tid; idx<64*64; idx+=256){
      int k=idx>>6, n=idx&63;
      st[k][n]=src[(size_t)(kc*64+k)*FF + nb*64 + n];
    }
    __syncthreads();
    for(int idx=tid; idx<64*32; idx+=256){
      int r=idx>>5, c2=idx&31;
      float x0=st[2*c2][r], x1=st[2*c2+1][r];
      __nv_bfloat16 h0,l0,h1,l1;
      split_bf16(x0,h0,l0); split_bf16(x1,h1,l1);
      uint32_t off=SWZ((uint32_t)((half*64+r)*128 + c2*4));
      __nv_bfloat162 vh; vh.x=h0; vh.y=h1;
      __nv_bfloat162 vl; vl.x=l0; vl.y=l1;
      *(__nv_bfloat162*)(th+off)=vh;
      *(__nv_bfloat162*)(tl+off)=vl;
    }
    __syncthreads();
  }
}
// ===== weight conversion: down tiles; tile=[128 rows(D)]x[64 k(F)] =====
__global__ void conv_wd_k(const float* __restrict__ wd){
  __shared__ float st[64][129];
  int kc=blockIdx.x, nb=blockIdx.y, e=blockIdx.z, tid=threadIdx.x;
  size_t toff=((size_t)(e*16+nb)*12 + kc)*8192;
  char* th=(char*)(g_wd_h+toff);
  char* tl=(char*)(g_wd_l+toff);
  const float* src=wd+(size_t)e*FF*DD;
  for(int idx=tid; idx<64*128; idx+=256){
    int k=idx>>7, n=idx&127;
    st[k][n]=src[(size_t)(kc*64+k)*DD + nb*128 + n];
  }
  __syncthreads();
  for(int idx=tid; idx<128*32; idx+=256){
    int r=idx>>5, c2=idx&31;
    float x0=st[2*c2][r], x1=st[2*c2+1][r];
    __nv_bfloat16 h0,l0,h1,l1;
    split_bf16(x0,h0,l0); split_bf16(x1,h1,l1);
    uint32_t off=SWZ((uint32_t)(r*128 + c2*4));
    __nv_bfloat162 vh; vh.x=h0; vh.y=h1;
    __nv_bfloat162 vl; vl.x=l0; vl.y=l1;
    *(__nv_bfloat162*)(th+off)=vh;
    *(__nv_bfloat162*)(tl+off)=vl;
  }
}
// ===== weight conversion: dense W[K][N] -> tiles [nb][kc] of [128 n][64 k] =====
__global__ void conv_dense_k(const float* __restrict__ src,
                             __nv_bfloat16* __restrict__ th_base,
                             __nv_bfloat16* __restrict__ tl_base, int N){
  __shared__ float st[64][129];
  int kc=blockIdx.x, nb=blockIdx.y, tid=threadIdx.x;
  size_t toff=((size_t)nb*32 + kc)*8192;
  char* th=(char*)(th_base+toff);
  char* tl=(char*)(tl_base+toff);
  for(int idx=tid; idx<64*128; idx+=256){
    int k=idx>>7, n=idx&127;
    st[k][n]=src[(size_t)(kc*64+k)*N + nb*128 + n];
  }
  __syncthreads();
  for(int idx=tid; idx<128*32; idx+=256){
    int r=idx>>5, c2=idx&31;
    float x0=st[2*c2][r], x1=st[2*c2+1][r];
    __nv_bfloat16 h0,l0,h1,l1;
    split_bf16(x0,h0,l0); split_bf16(x1,h1,l1);
    uint32_t off=SWZ((uint32_t)(r*128 + c2*4));
    __nv_bfloat162 vh; vh.x=h0; vh.y=h1;
    __nv_bfloat162 vl; vl.x=l0; vl.y=l1;
    *(__nv_bfloat162*)(th+off)=vh;
    *(__nv_bfloat162*)(tl+off)=vl;
  }
}

// ===== dense mma core: 128x128 tile, K=2048 (32 chunks), A rows sequential =====
__device__ __forceinline__ void dense_mma_core(
    char* smraw, uint32_t smb, int tid, int lane, int w, int m0,
    const __nv_bfloat16* Ah_g, const __nv_bfloat16* Al_g,
    const char* BhW, const char* BlW, float acc[2][8][4]){
  int mrow=(w&3)*32, ncol=(w>>2)*64;
  {
    for(int idx=tid; idx<1024; idx+=256){
      int r=idx>>3, c=idx&7;
      size_t src=(size_t)(m0+r)*DD + c*8;
      uint32_t d=SWZ((uint32_t)(r*128+c*16));
      CP_ASYNC16(smb+MMS_TILE(0,0)+d, (const char*)(Ah_g+src));
      CP_ASYNC16(smb+MMS_TILE(0,1)+d, (const char*)(Al_g+src));
      CP_ASYNC16(smb+MMS_TILE(0,2)+idx*16, BhW+idx*16);
      CP_ASYNC16(smb+MMS_TILE(0,3)+idx*16, BlW+idx*16);
    }
    CP_COMMIT();
  }
  for(int kc=0;kc<32;kc++){
    int s=kc&1;
    if(kc+1<32){
      int ns=s^1, nk=kc+1;
      for(int idx=tid; idx<1024; idx+=256){
        int r=idx>>3, c=idx&7;
        size_t src=(size_t)(m0+r)*DD + nk*64 + c*8;
        uint32_t d=SWZ((uint32_t)(r*128+c*16));
        CP_ASYNC16(smb+MMS_TILE(ns,0)+d, (const char*)(Ah_g+src));
        CP_ASYNC16(smb+MMS_TILE(ns,1)+d, (const char*)(Al_g+src));
        CP_ASYNC16(smb+MMS_TILE(ns,2)+idx*16, BhW+(size_t)nk*16384+idx*16);
        CP_ASYNC16(smb+MMS_TILE(ns,3)+idx*16, BlW+(size_t)nk*16384+idx*16);
      }
    }
    CP_COMMIT();
    CP_WAIT1();
    __syncthreads();
    uint32_t Ah=smb+MMS_TILE(s,0), Al=smb+MMS_TILE(s,1);
    uint32_t Bh=smb+MMS_TILE(s,2), Bl=smb+MMS_TILE(s,3);
    #pragma unroll
    for(int ks=0;ks<4;ks++){
      uint32_t ah[2][4], al[2][4];
      #pragma unroll
      for(int mt=0;mt<2;mt++){
        uint32_t ra=SWZ((uint32_t)((mrow+mt*16+(lane&15))*128 + ks*32 + ((lane>>4)<<4)));
        LDM4(ah[mt], Ah+ra);
        LDM4(al[mt], Al+ra);
      }
      #pragma unroll
      for(int np=0;np<4;np++){
        uint32_t rb=SWZ((uint32_t)((ncol+np*16+(lane&15))*128 + ks*32 + ((lane>>4)<<4)));
        uint32_t bh[4], bl[4];
        LDM4(bh, Bh+rb);
        LDM4(bl, Bl+rb);
        #pragma unroll
        for(int sub=0;sub<2;sub++){
          int nt=np*2+sub;
          #pragma unroll
          for(int mt=0;mt<2;mt++){
            MMA_BF16(acc[mt][nt], ah[mt], bh[sub], bh[sub+2]);
            MMA_BF16(acc[mt][nt], ah[mt], bl[sub], bl[sub+2]);
            MMA_BF16(acc[mt][nt], al[mt], bh[sub], bh[sub+2]);
          }
        }
      }
    }
    __syncthreads();
  }
}

// ====== qkv projections via mma bf16x3; grid (24, TT/128) ======
__global__ void __launch_bounds__(256,1) sgemm_qkv_mma(){
  extern __shared__ char smraw[];
  int tid=threadIdx.x, lane=tid&31, w=tid>>5;
  int nb=blockIdx.x, m0=blockIdx.y<<7;
  float* C; int Nc;
  if(nb<16){ C=g_q + nb*128; Nc=QSTR; }
  else if(nb<20){ C=g_kb + (nb-16)*128; Nc=KSTR; }
  else { C=g_vb + (nb-20)*128; Nc=KSTR; }
  const char* BhW=(const char*)(g_wqkv_h + (size_t)nb*32*8192);
  const char* BlW=(const char*)(g_wqkv_l + (size_t)nb*32*8192);
  uint32_t smb=smem_u32(smraw);
  float acc[2][8][4]={};
  dense_mma_core(smraw, smb, tid, lane, w, m0, g_ht_h, g_ht_l, BhW, BlW, acc);
  int mrow=(w&3)*32, ncol=(w>>2)*64;
  #pragma unroll
  for(int mt=0;mt<2;mt++)
    #pragma unroll
    for(int dr=0;dr<2;dr++){
      int rr=mrow+mt*16+(lane>>2)+dr*8;
      #pragma unroll
      for(int nt=0;nt<8;nt++){
        int col=ncol+nt*8+(lane&3)*2;
        float2 v={acc[mt][nt][dr*2], acc[mt][nt][dr*2+1]};
        *(float2*)(C+(size_t)(m0+rr)*Nc + col)=v;
      }
    }
}

// ====== wo projection + residual via mma bf16x3; grid (16, TT/128) ======
__global__ void __launch_bounds__(256,1) sgemm_wo_mma(const float* __restrict__ xres,
                                                      float* __restrict__ out){
  extern __shared__ char smraw[];
  int tid=threadIdx.x, lane=tid&31, w=tid>>5;
  int nb=blockIdx.x, m0=blockIdx.y<<7;
  const char* BhW=(const char*)(g_wo_h + (size_t)nb*32*8192);
  const char* BlW=(const char*)(g_wo_l + (size_t)nb*32*8192);
  uint32_t smb=smem_u32(smraw);
  float acc[2][8][4]={};
  dense_mma_core(smraw, smb, tid, lane, w, m0, g_o_h, g_o_l, BhW, BlW, acc);
  int mrow=(w&3)*32, ncol=(w>>2)*64;
  #pragma unroll
  for(int mt=0;mt<2;mt++)
    #pragma unroll
    for(int dr=0;dr<2;dr++){
      int rr=mrow+mt*16+(lane>>2)+dr*8;
      #pragma unroll
      for(int nt=0;nt<8;nt++){
        int col=ncol+nt*8+(lane&3)*2;
        size_t off=(size_t)(m0+rr)*DD + nb*128 + col;
        float2 c2v=*(const float2*)(xres+off);
        float2 v={acc[mt][nt][dr*2]+c2v.x, acc[mt][nt][dr*2+1]+c2v.y};
        *(float2*)(out+off)=v;
      }
    }
}

__global__ void qknorm_rope_k(const float* __restrict__ cosp, const float* __restrict__ sinp,
                              const float* __restrict__ qnw, const float* __restrict__ knw){
  int t=blockIdx.x, yy=blockIdx.y, i=threadIdx.x;
  float* ptr; const float* w;
  if(yy<HH){ ptr=g_q +(size_t)t*QSTR+yy*HDD; w=qnw; }
  else     { ptr=g_kb+(size_t)t*KSTR+(yy-HH)*HDD; w=knw; }
  float v=ptr[i];
  float ss=v*v;
  #pragma unroll
  for(int off=16;off;off>>=1) ss+=__shfl_xor_sync(0xffffffffu,ss,off);
  __shared__ float red[4];
  __shared__ float sh[HDD];
  if((i&31)==0) red[i>>5]=ss;
  __syncthreads();
  float tot=red[0]+red[1]+red[2]+red[3];
  float n=v*rsqrtf(tot/(float)HDD + 1e-6f)*w[i];
  sh[i]=n;
  __syncthreads();
  float rot=(i<64)? -sh[i+64] : sh[i-64];
  ptr[i]= n*cosp[(size_t)t*HDD+i] + rot*sinp[(size_t)t*HDD+i];
}

#define FLASH_SMEM ((3*64*132 + 64*68)*4)
__global__ void __launch_bounds__(256,1) flash_k(){
  extern __shared__ float smf[];
  float* Qs=smf;
  float* Ks=smf+64*132;
  float* Vs=smf+2*64*132;
  float* Ps=smf+3*64*132;
  int tid=threadIdx.x, tx=tid&15, ty=tid>>4;
  int bh=blockIdx.y; int b=bh>>4, h=bh&15, kh=(bh&15)>>2;
  int qs0=((SS/64-1)-blockIdx.x)<<6;
  const float scale=0.08838834764831845f;
  for(int i=tid;i<64*32;i+=256){
    int r=i>>5, c=(i&31)<<2;
    float4 qv=*(const float4*)(g_q + (size_t)(b*SS+qs0+r)*QSTR + h*HDD + c);
    qv.x*=scale; qv.y*=scale; qv.z*=scale; qv.w*=scale;
    *(float4*)&Qs[r*132+c]=qv;
  }
  float m_r[4], l_r[4], O[4][8];
  #pragma unroll
  for(int i=0;i<4;i++){ m_r[i]=-1e30f; l_r[i]=0.f;
    #pragma unroll
    for(int c=0;c<8;c++) O[i][c]=0.f; }
  for(int j0=0;j0<=qs0;j0+=64){
    for(int i=tid;i<64*32;i+=256){
      int r=i>>5, c=(i&31)<<2;
      size_t kvoff=(size_t)(b*SS+j0+r)*KSTR + kh*HDD + c;
      *(float4*)&Ks[r*132+c]=*(const float4*)(g_kb + kvoff);
      *(float4*)&Vs[r*132+c]=*(const float4*)(g_vb + kvoff);
    }
    __syncthreads();
    float s[4][4]={};
    #pragma unroll 8
    for(int d=0;d<128;d+=4){
      float4 a0=*(float4*)&Qs[((ty<<2)+0)*132+d];
      float4 a1=*(float4*)&Qs[((ty<<2)+1)*132+d];
      float4 a2=*(float4*)&Qs[((ty<<2)+2)*132+d];
      float4 a3=*(float4*)&Qs[((ty<<2)+3)*132+d];
      float4 b0=*(float4*)&Ks[(tx   )*132+d];
      float4 b1=*(float4*)&Ks[(tx+16)*132+d];
      float4 b2=*(float4*)&Ks[(tx+32)*132+d];
      float4 b3=*(float4*)&Ks[(tx+48)*132+d];
      s[0][0]+=a0.x*b0.x+a0.y*b0.y+a0.z*b0.z+a0.w*b0.w;
      s[0][1]+=a0.x*b1.x+a0.y*b1.y+a0.z*b1.z+a0.w*b1.w;
      s[0][2]+=a0.x*b2.x+a0.y*b2.y+a0.z*b2.z+a0.w*b2.w;
      s[0][3]+=a0.x*b3.x+a0.y*b3.y+a0.z*b3.z+a0.w*b3.w;
      s[1][0]+=a1.x*b0.x+a1.y*b0.y+a1.z*b0.z+a1.w*b0.w;
      s[1][1]+=a1.x*b1.x+a1.y*b1.y+a1.z*b1.z+a1.w*b1.w;
      s[1][2]+=a1.x*b2.x+a1.y*b2.y+a1.z*b2.z+a1.w*b2.w;
      s[1][3]+=a1.x*b3.x+a1.y*b3.y+a1.z*b3.z+a1.w*b3.w;
      s[2][0]+=a2.x*b0.x+a2.y*b0.y+a2.z*b0.z+a2.w*b0.w;
      s[2][1]+=a2.x*b1.x+a2.y*b1.y+a2.z*b1.z+a2.w*b1.w;
      s[2][2]+=a2.x*b2.x+a2.y*b2.y+a2.z*b2.z+a2.w*b2.w;
      s[2][3]+=a2.x*b3.x+a2.y*b3.y+a2.z*b3.z+a2.w*b3.w;
      s[3][0]+=a3.x*b0.x+a3.y*b0.y+a3.z*b0.z+a3.w*b0.w;
      s[3][1]+=a3.x*b1.x+a3.y*b1.y+a3.z*b1.z+a3.w*b1.w;
      s[3][2]+=a3.x*b2.x+a3.y*b2.y+a3.z*b2.z+a3.w*b2.w;
      s[3][3]+=a3.x*b3.x+a3.y*b3.y+a3.z*b3.z+a3.w*b3.w;
    }
    if(j0==qs0){
      #pragma unroll
      for(int i=0;i<4;i++)
        #pragma unroll
        for(int j=0;j<4;j++)
          if(tx + (j<<4) > (ty<<2)+i) s[i][j]=-1e30f;
    }
    #pragma unroll
    for(int i=0;i<4;i++){
      float mx=fmaxf(fmaxf(s[i][0],s[i][1]),fmaxf(s[i][2],s[i][3]));
      #pragma unroll
      for(int off=8;off;off>>=1) mx=fmaxf(mx,__shfl_xor_sync(0xffffffffu,mx,off));
      float mn=fmaxf(m_r[i],mx);
      float sc=__expf(m_r[i]-mn);
      float rs=0.f;
      #pragma unroll
      for(int j=0;j<4;j++){ float p=__expf(s[i][j]-mn); s[i][j]=p; rs+=p; }
      #pragma unroll
      for(int off=8;off;off>>=1) rs+=__shfl_xor_sync(0xffffffffu,rs,off);
      l_r[i]=l_r[i]*sc+rs; m_r[i]=mn;
      #pragma unroll
      for(int c=0;c<8;c++) O[i][c]*=sc;
      #pragma unroll
      for(int j=0;j<4;j++) Ps[((ty<<2)+i)*68 + tx + (j<<4)] = s[i][j];
    }
    __syncthreads();
    #pragma unroll 2
    for(int jj=0;jj<64;jj++){
      float p0=Ps[((ty<<2)+0)*68+jj];
      float p1=Ps[((ty<<2)+1)*68+jj];
      float p2=Ps[((ty<<2)+2)*68+jj];
      float p3=Ps[((ty<<2)+3)*68+jj];
      float4 va=*(float4*)&Vs[jj*132+(tx<<3)];
      float4 vb=*(float4*)&Vs[jj*132+(tx<<3)+4];
      O[0][0]+=p0*va.x; O[0][1]+=p0*va.y; O[0][2]+=p0*va.z; O[0][3]+=p0*va.w;
      O[0][4]+=p0*vb.x; O[0][5]+=p0*vb.y; O[0][6]+=p0*vb.z; O[0][7]+=p0*vb.w;
      O[1][0]+=p1*va.x; O[1][1]+=p1*va.y; O[1][2]+=p1*va.z; O[1][3]+=p1*va.w;
      O[1][4]+=p1*vb.x; O[1][5]+=p1*vb.y; O[1][6]+=p1*vb.z; O[1][7]+=p1*vb.w;
      O[2][0]+=p2*va.x; O[2][1]+=p2*va.y; O[2][2]+=p2*va.z; O[2][3]+=p2*va.w;
      O[2][4]+=p2*vb.x; O[2][5]+=p2*vb.y; O[2][6]+=p2*vb.z; O[2][7]+=p2*vb.w;
      O[3][0]+=p3*va.x; O[3][1]+=p3*va.y; O[3][2]+=p3*va.z; O[3][3]+=p3*va.w;
      O[3][4]+=p3*vb.x; O[3][5]+=p3*vb.y; O[3][6]+=p3*vb.z; O[3][7]+=p3*vb.w;
    }
    __syncthreads();
  }
  #pragma unroll
  for(int i=0;i<4;i++){
    float inv=1.f/l_r[i];
    size_t obase=(size_t)(b*SS+qs0+(ty<<2)+i)*QSTR + h*HDD + (tx<<3);
    float vals[8];
    #pragma unroll
    for(int c=0;c<8;c++) vals[c]=O[i][c]*inv;
    float4 r0={vals[0],vals[1],vals[2],vals[3]};
    float4 r1={vals[4],vals[5],vals[6],vals[7]};
    *(float4*)(g_o+obase)=r0; *(float4*)(g_o+obase+4)=r1;
    #pragma unroll
    for(int c=0;c<8;c+=2){
      __nv_bfloat16 h0,l0,h1,l1;
      split_bf16(vals[c],h0,l0); split_bf16(vals[c+1],h1,l1);
      __nv_bfloat162 vh; vh.x=h0; vh.y=h1;
      __nv_bfloat162 vl; vl.x=l0; vl.y=l1;
      *(__nv_bfloat162*)(g_o_h+obase+c)=vh;
      *(__nv_bfloat162*)(g_o_l+obase+c)=vl;
    }
  }
}

__global__ void router_topk_k(const float* __restrict__ rw){
  __shared__ float sh[DD];
  __shared__ float lg[EE];
  int t=blockIdx.x, e=threadIdx.x;
  if(e==0 && t<EE) g_cnt[t]=0;
  float4* sh4=(float4*)sh;
  const float4* h4=(const float4*)(g_ht+(size_t)t*DD);
  for(int i=e;i<DD/4;i+=EE) sh4[i]=h4[i];
  __syncthreads();
  float acc=0.f;
  #pragma unroll 4
  for(int d=0;d<DD;d++) acc += sh[d]*rw[(size_t)d*EE+e];
  lg[e]=acc;
  __syncthreads();
  if(e==0){
    float mx=-1e30f;
    for(int i=0;i<EE;i++) mx=fmaxf(mx,lg[i]);
    for(int i=0;i<EE;i++) lg[i]=__expf(lg[i]-mx);
    int ti[TOPKK]; float tv[TOPKK]; float s8=0.f;
    for(int k2=0;k2<TOPKK;k2++){
      float best=-1.f; int bi=0;
      for(int i=0;i<EE;i++) if(lg[i]>best){best=lg[i];bi=i;}
      ti[k2]=bi; tv[k2]=best; s8+=best; lg[bi]=-2.f;
    }
    float inv=1.f/s8;
    for(int k2=0;k2<TOPKK;k2++){ g_topi[t*TOPKK+k2]=ti[k2]; g_topv[t*TOPKK+k2]=tv[k2]*inv; }
  }
}

__global__ void assign_k(){
  int p=blockIdx.x*256+threadIdx.x;
  if(p<TT*TOPKK){
    int e=g_topi[p];
    int pos=atomicAdd(&g_cnt[e],1);
    g_list[e*TT+pos]=p;
  }
}

// ====== MoE gate+up via mma.sync bf16x3; CTA=(nb in F/64, e) ======
__global__ void __launch_bounds__(256,1) moe_gateup_mma(){
  extern __shared__ char smraw[];
  int tid=threadIdx.x, lane=tid&31, w=tid>>5;
  int nb=blockIdx.x, e=blockIdx.y;
  int ce=g_cnt[e]; if(ce==0) return;
  uint32_t smb=smem_u32(smraw);
  int* spair_s=(int*)smraw;
  int* stok_s =(int*)(smraw+512);
  const char* BhW=(const char*)(g_wgu_h + (size_t)(e*12+nb)*32*8192);
  const char* BlW=(const char*)(g_wgu_l + (size_t)(e*12+nb)*32*8192);
  int mrow=(w&3)*32, ncol=(w>>2)*32;

  for(int m0=0;m0<ce;m0+=128){
    if(tid<128){
      int idx=m0+tid;
      int p=(idx<ce)? g_list[e*TT+idx] : -1;
      spair_s[tid]=p; stok_s[tid]=(p>=0)?(p>>3):0;
    }
    __syncthreads();
    float accg[2][4][4]={}, accu[2][4][4]={};
    {
      for(int idx=tid; idx<1024; idx+=256){
        int r=idx>>3, c=idx&7;
        size_t src=(size_t)stok_s[r]*DD + c*8;
        uint32_t d=SWZ((uint32_t)(r*128+c*16));
        CP_ASYNC16(smb+MMS_TILE(0,0)+d, (const char*)(g_ht_h+src));
        CP_ASYNC16(smb+MMS_TILE(0,1)+d, (const char*)(g_ht_l+src));
        CP_ASYNC16(smb+MMS_TILE(0,2)+idx*16, BhW+idx*16);
        CP_ASYNC16(smb+MMS_TILE(0,3)+idx*16, BlW+idx*16);
      }
      CP_COMMIT();
    }
    for(int kc=0;kc<32;kc++){
      int s=kc&1;
      if(kc+1<32){
        int ns=s^1, nk=kc+1;
        for(int idx=tid; idx<1024; idx+=256){
          int r=idx>>3, c=idx&7;
          size_t src=(size_t)stok_s[r]*DD + nk*64 + c*8;
          uint32_t d=SWZ((uint32_t)(r*128+c*16));
          CP_ASYNC16(smb+MMS_TILE(ns,0)+d, (const char*)(g_ht_h+src));
          CP_ASYNC16(smb+MMS_TILE(ns,1)+d, (const char*)(g_ht_l+src));
          CP_ASYNC16(smb+MMS_TILE(ns,2)+idx*16, BhW+(size_t)nk*16384+idx*16);
          CP_ASYNC16(smb+MMS_TILE(ns,3)+idx*16, BlW+(size_t)nk*16384+idx*16);
        }
      }
      CP_COMMIT();
      CP_WAIT1();
      __syncthreads();
      uint32_t Ah=smb+MMS_TILE(s,0), Al=smb+MMS_TILE(s,1);
      uint32_t Bh=smb+MMS_TILE(s,2), Bl=smb+MMS_TILE(s,3);
      #pragma unroll
      for(int ks=0;ks<4;ks++){
        uint32_t ah[2][4], al[2][4];
        #pragma unroll
        for(int mt=0;mt<2;mt++){
          uint32_t ra=SWZ((uint32_t)((mrow+mt*16+(lane&15))*128 + ks*32 + ((lane>>4)<<4)));
          LDM4(ah[mt], Ah+ra);
          LDM4(al[mt], Al+ra);
        }
        #pragma unroll
        for(int half=0;half<2;half++){
          #pragma unroll
          for(int np=0;np<2;np++){
            uint32_t rb=SWZ((uint32_t)((half*64+ncol+np*16+(lane&15))*128 + ks*32 + ((lane>>4)<<4)));
            uint32_t bh[4], bl[4];
            LDM4(bh, Bh+rb);
            LDM4(bl, Bl+rb);
            #pragma unroll
            for(int sub=0;sub<2;sub++){
              int nt=np*2+sub;
              #pragma unroll
              for(int mt=0;mt<2;mt++){
                float* acc = half? accu[mt][nt] : accg[mt][nt];
                MMA_BF16(acc, ah[mt], bh[sub], bh[sub+2]);
                MMA_BF16(acc, ah[mt], bl[sub], bl[sub+2]);
                MMA_BF16(acc, al[mt], bh[sub], bh[sub+2]);
              }
            }
          }
        }
      }
      __syncthreads();
    }
    // epilogue: silu(g)*u -> bf16 hi/lo
    #pragma unroll
    for(int mt=0;mt<2;mt++){
      #pragma unroll
      for(int dr=0;dr<2;dr++){
        int rr=mrow+mt*16+(lane>>2)+dr*8;
        int p=spair_s[rr];
        if(p>=0){
          #pragma unroll
          for(int nt=0;nt<4;nt++){
            int col=ncol+nt*8+(lane&3)*2;
            float g0=accg[mt][nt][dr*2],   g1=accg[mt][nt][dr*2+1];
            float u0=accu[mt][nt][dr*2],   u1=accu[mt][nt][dr*2+1];
            float a0=(g0/(1.f+__expf(-g0)))*u0;
            float a1=(g1/(1.f+__expf(-g1)))*u1;
            __nv_bfloat16 h0,l0,h1,l1;
            split_bf16(a0,h0,l0); split_bf16(a1,h1,l1);
            __nv_bfloat162 vh; vh.x=h0; vh.y=h1;
            __nv_bfloat162 vl; vl.x=l0; vl.y=l1;
            size_t o=(size_t)p*FF + nb*64 + col;
            *(__nv_bfloat162*)(g_act_h+o)=vh;
            *(__nv_bfloat162*)(g_act_l+o)=vl;
          }
        }
      }
    }
    __syncthreads();
  }
}

// ====== MoE down via mma.sync bf16x3; CTA=(nb in D/128, e) ======
__global__ void __launch_bounds__(256,1) moe_down_mma(){
  extern __shared__ char smraw[];
  int tid=threadIdx.x, lane=tid&31, w=tid>>5;
  int nb=blockIdx.x, e=blockIdx.y;
  int ce=g_cnt[e]; if(ce==0) return;
  uint32_t smb=smem_u32(smraw);
  int* spair_s=(int*)smraw;
  const char* BhW=(const char*)(g_wd_h + (size_t)(e*16+nb)*12*8192);
  const char* BlW=(const char*)(g_wd_l + (size_t)(e*16+nb)*12*8192);
  int mrow=(w&3)*32, ncol=(w>>2)*64;

  for(int m0=0;m0<ce;m0+=128){
    if(tid<128){
      int idx=m0+tid;
      spair_s[tid]=(idx<ce)? g_list[e*TT+idx] : -1;
    }
    __syncthreads();
    float acc[2][8][4]={};
    {
      for(int idx=tid; idx<1024; idx+=256){
        int r=idx>>3, c=idx&7;
        int p=spair_s[r]; if(p<0) p=0;
        size_t src=(size_t)p*FF + c*8;
        uint32_t d=SWZ((uint32_t)(r*128+c*16));
        CP_ASYNC16(smb+MMS_TILE(0,0)+d, (const char*)(g_act_h+src));
        CP_ASYNC16(smb+MMS_TILE(0,1)+d, (const char*)(g_act_l+src));
        CP_ASYNC16(smb+MMS_TILE(0,2)+idx*16, BhW+idx*16);
        CP_ASYNC16(smb+MMS_TILE(0,3)+idx*16, BlW+idx*16);
      }
      CP_COMMIT();
    }
    for(int kc=0;kc<12;kc++){
      int s=kc&1;
      if(kc+1<12){
        int ns=s^1, nk=kc+1;
        for(int idx=tid; idx<1024; idx+=256){
          int r=idx>>3, c=idx&7;
          int p=spair_s[r]; if(p<0) p=0;
          size_t src=(size_t)p*FF + nk*64 + c*8;
          uint32_t d=SWZ((uint32_t)(r*128+c*16));
          CP_ASYNC16(smb+MMS_TILE(ns,0)+d, (const char*)(g_act_h+src));
          CP_ASYNC16(smb+MMS_TILE(ns,1)+d, (const char*)(g_act_l+src));
          CP_ASYNC16(smb+MMS_TILE(ns,2)+idx*16, BhW+(size_t)nk*16384+idx*16);
          CP_ASYNC16(smb+MMS_TILE(ns,3)+idx*16, BlW+(size_t)nk*16384+idx*16);
        }
      }
      CP_COMMIT();
      CP_WAIT1();
      __syncthreads();
      uint32_t Ah=smb+MMS_TILE(s,0), Al=smb+MMS_TILE(s,1);
      uint32_t Bh=smb+MMS_TILE(s,2), Bl=smb+MMS_TILE(s,3);
      #pragma unroll
      for(int ks=0;ks<4;ks++){
        uint32_t ah[2][4], al[2][4];
        #pragma unroll
        for(int mt=0;mt<2;mt++){
          uint32_t ra=SWZ((uint32_t)((mrow+mt*16+(lane&15))*128 + ks*32 + ((lane>>4)<<4)));
          LDM4(ah[mt], Ah+ra);
          LDM4(al[mt], Al+ra);
        }
        #pragma unroll
        for(int np=0;np<4;np++){
          uint32_t rb=SWZ((uint32_t)((ncol+np*16+(lane&15))*128 + ks*32 + ((lane>>4)<<4)));
          uint32_t bh[4], bl[4];
          LDM4(bh, Bh+rb);
          LDM4(bl, Bl+rb);
          #pragma unroll
          for(int sub=0;sub<2;sub++){
            int nt=np*2+sub;
            #pragma unroll
            for(int mt=0;mt<2;mt++){
              MMA_BF16(acc[mt][nt], ah[mt], bh[sub], bh[sub+2]);
              MMA_BF16(acc[mt][nt], ah[mt], bl[sub], bl[sub+2]);
              MMA_BF16(acc[mt][nt], al[mt], bh[sub], bh[sub+2]);
            }
          }
        }
      }
      __syncthreads();
    }
    #pragma unroll
    for(int mt=0;mt<2;mt++){
      #pragma unroll
      for(int dr=0;dr<2;dr++){
        int rr=mrow+mt*16+(lane>>2)+dr*8;
        int p=spair_s[rr];
        if(p>=0){
          #pragma unroll
          for(int nt=0;nt<8;nt++){
            int col=ncol+nt*8+(lane&3)*2;
            float2 v={acc[mt][nt][dr*2], acc[mt][nt][dr*2+1]};
            *(float2*)(g_y+(size_t)p*DD + nb*128 + col)=v;
          }
        }
      }
    }
    __syncthreads();
  }
}

__global__ void combine_k(float* __restrict__ out){
  int t=blockIdx.x;
  __shared__ float w8[TOPKK];
  if(threadIdx.x<TOPKK) w8[threadIdx.x]=g_topv[t*TOPKK+threadIdx.x];
  __syncthreads();
  float4* o4=(float4*)(out+(size_t)t*DD);
  for(int c=threadIdx.x;c<DD/4;c+=blockDim.x){
    float4 a=o4[c];
    #pragma unroll
    for(int k=0;k<TOPKK;k++){
      float wk_=w8[k];
      float4 yv=((const float4*)(g_y+(size_t)(t*TOPKK+k)*DD))[c];
      a.x+=wk_*yv.x; a.y+=wk_*yv.y; a.z+=wk_*yv.z; a.w+=wk_*yv.w;
    }
    o4[c]=a;
  }
}

// =================================================================
extern "C" void kernel_launch(void* const* d_in, const int* in_sizes, int n_in,
                              void* d_out, int out_size){
  const float* x   =(const float*)d_in[0];
  const float* cosp=(const float*)d_in[1];
  const float* sinp=(const float*)d_in[2];
  const float* ln1 =(const float*)d_in[3];
  const float* wq  =(const float*)d_in[4];
  const float* wk  =(const float*)d_in[5];
  const float* wv  =(const float*)d_in[6];
  const float* wo  =(const float*)d_in[7];
  const float* qnw =(const float*)d_in[8];
  const float* knw =(const float*)d_in[9];
  const float* ln2 =(const float*)d_in[10];
  const float* rw  =(const float*)d_in[11];
  const float* wg  =(const float*)d_in[12];
  const float* wu  =(const float*)d_in[13];
  const float* wd  =(const float*)d_in[14];
  float* out=(float*)d_out;

  float *ph,*pht;
  __nv_bfloat16 *pwqkv_h,*pwqkv_l,*pwo_h,*pwo_l;
  cudaGetSymbolAddress((void**)&ph,  g_h);
  cudaGetSymbolAddress((void**)&pht, g_ht);
  cudaGetSymbolAddress((void**)&pwqkv_h, g_wqkv_h);
  cudaGetSymbolAddress((void**)&pwqkv_l, g_wqkv_l);
  cudaGetSymbolAddress((void**)&pwo_h,   g_wo_h);
  cudaGetSymbolAddress((void**)&pwo_l,   g_wo_l);

  cudaFuncSetAttribute(flash_k, cudaFuncAttributeMaxDynamicSharedMemorySize, FLASH_SMEM);
  cudaFuncSetAttribute(moe_gateup_mma, cudaFuncAttributeMaxDynamicSharedMemorySize, MMS_TOTAL);
  cudaFuncSetAttribute(moe_down_mma,   cudaFuncAttributeMaxDynamicSharedMemorySize, MMS_TOTAL);
  cudaFuncSetAttribute(sgemm_qkv_mma,  cudaFuncAttributeMaxDynamicSharedMemorySize, MMS_TOTAL);
  cudaFuncSetAttribute(sgemm_wo_mma,   cudaFuncAttributeMaxDynamicSharedMemorySize, MMS_TOTAL);

  // 0) weight conversions -> bf16 hi/lo pre-swizzled tiles
  conv_gu_k<<<dim3(32,12,EE),256>>>(wg, wu);
  conv_wd_k<<<dim3(12,16,EE),256>>>(wd);
  conv_dense_k<<<dim3(32,16),256>>>(wq, pwqkv_h,              pwqkv_l,              QSTR);
  conv_dense_k<<<dim3(32,4),256>>>(wk, pwqkv_h+(size_t)16*32*8192, pwqkv_l+(size_t)16*32*8192, KSTR);
  conv_dense_k<<<dim3(32,4),256>>>(wv, pwqkv_h+(size_t)20*32*8192, pwqkv_l+(size_t)20*32*8192, KSTR);
  conv_dense_k<<<dim3(32,16),256>>>(wo, pwo_h, pwo_l, DD);
  // 1) h = rmsnorm(x); bf16 hi/lo into g_ht_h/l (scratch until rmsnorm2)
  rmsnorm_k<<<TT,256>>>(x, ln1, ph, 1);
  // 2) q,k,v projections on tensor cores
  sgemm_qkv_mma<<<dim3(24, TT/128),256,MMS_TOTAL>>>();
  // 3) per-head rmsnorm + rope
  qknorm_rope_k<<<dim3(TT, HH+KVHH),128>>>(cosp, sinp, qnw, knw);
  // 4) causal flash attention (emits g_o fp32 + hi/lo)
  flash_k<<<dim3(SS/64, BB*HH),256, FLASH_SMEM>>>();
  // 5) x1 = x + o @ wo on tensor cores (into d_out)
  sgemm_wo_mma<<<dim3(16, TT/128),256,MMS_TOTAL>>>(x, out);
  // 6) ht = rmsnorm(x1); bf16 hi/lo for MoE
  rmsnorm_k<<<TT,256>>>(out, ln2, pht, 1);
  // 7) router + top-8 (also zeroes g_cnt)
  router_topk_k<<<TT,EE>>>(rw);
  // 8) expert pair lists
  assign_k<<<(TT*TOPKK+255)/256,256>>>();
  // 9) MoE on tensor cores
  moe_gateup_mma<<<dim3(12,EE),256,MMS_TOTAL>>>();
  moe_down_mma  <<<dim3(16,EE),256,MMS_TOTAL>>>();
  // 10) out = x1 + weighted expert sum
  combine_k<<<TT,256>>>(out);
}